// round 8
// baseline (speedup 1.0000x reference)
#include <cuda_runtime.h>
#include <cstdint>

// CarryLSTMModel: B=8192, T=1024, D=16, H=16 (4H=64 gates, order i,f,g,o)
// Split-K, 4 elements per warp (A,B,C,D):
//   lanes 0-15  hold Wi (x-part) weights for gate cols {j,j+16,j+32,j+48},
//   lanes 16-31 hold Wh (h-part) weights for the same cols.
// Each lane computes partial z for ALL 4 elements (128 FFMA2/warp-step).
// shfl_xor(16) combines partials AND redistributes: low lanes finalize A,B;
// high lanes finalize C,D -> every lane runs TWO independent recurrence
// chains (ILP in the serial tail). Weights shared across elements: 64 regs.
// Operands loaded as ld.shared.v2.u64 (no pack movs). x staged via cp.async.
// Activations: MUFU.TANH, sig(z)=0.5+0.5*tanh(z/2) (weights pre-scaled).

#define NB 8192
#define NT 1024
#define ND 16
#define NG 64

typedef unsigned long long u64;
typedef unsigned int u32;

__device__ __forceinline__ u64 pack2(float lo, float hi) {
    u64 r;
    asm("mov.b64 %0, {%1, %2};" : "=l"(r) : "r"(__float_as_uint(lo)), "r"(__float_as_uint(hi)));
    return r;
}
__device__ __forceinline__ void unpack2(u64 v, float& lo, float& hi) {
    u32 a, b;
    asm("mov.b64 {%0, %1}, %2;" : "=r"(a), "=r"(b) : "l"(v));
    lo = __uint_as_float(a);
    hi = __uint_as_float(b);
}
__device__ __forceinline__ u64 ffma2(u64 a, u64 b, u64 c) {
    u64 d;
    asm("fma.rn.f32x2 %0, %1, %2, %3;" : "=l"(d) : "l"(a), "l"(b), "l"(c));
    return d;
}
__device__ __forceinline__ float tanhap(float x) {
    float r; asm("tanh.approx.f32 %0, %1;" : "=f"(r) : "f"(x)); return r;
}
__device__ __forceinline__ float ex2f(float x) {
    float r; asm("ex2.approx.f32 %0, %1;" : "=f"(r) : "f"(x)); return r;
}
__device__ __forceinline__ float rcpf(float x) {
    float r; asm("rcp.approx.f32 %0, %1;" : "=f"(r) : "f"(x)); return r;
}
__device__ __forceinline__ u32 smem_u32(const void* p) {
    return (u32)__cvta_generic_to_shared(p);
}
__device__ __forceinline__ void lds_v2u64(u64& a, u64& b, u32 addr) {
    asm volatile("ld.shared.v2.u64 {%0, %1}, [%2];" : "=l"(a), "=l"(b) : "r"(addr));
}

__global__ __launch_bounds__(128, 3)
void lstm_fused_kernel(const float* __restrict__ x,
                       const float* __restrict__ Wi,
                       const float* __restrict__ Wh,
                       const float* __restrict__ bias,
                       const float* __restrict__ Wd,
                       const float* __restrict__ bd,
                       float* __restrict__ out)
{
    // staging, identical shapes so stride math is shared:
    // xsm[buf][warp][elem(4)][k(16)], hsm likewise. 2 KB each.
    __shared__ float xsm[2][4][4][16];
    __shared__ float hsm[2][4][4][16];

    const int wib  = threadIdx.x >> 5;
    const int lane = threadIdx.x & 31;
    const int half = lane >> 4;      // 0 = x-group (Wi), 1 = h-group (Wh)
    const int j    = lane & 15;      // gate index / hidden index
    const int e0   = blockIdx.x * 16 + wib * 4;   // elements A..D = e0..e0+3

    // sig(z) = 0.5 + 0.5*tanh(z/2): weights/bias pre-scaled so z is the tanh arg.
    const float sI = 0.5f, sF = 0.5f, sG = 1.0f, sO = 0.5f;
    const int ci = j, cf = j + 16, cg = j + 32, co = j + 48;

    const float* Wsrc = (half == 0) ? Wi : Wh;
    u64 wI[8], wF[8], wG[8], wO[8];
#pragma unroll
    for (int m = 0; m < 8; ++m) {
        wI[m] = pack2(Wsrc[(2*m) * NG + ci] * sI, Wsrc[(2*m+1) * NG + ci] * sI);
        wF[m] = pack2(Wsrc[(2*m) * NG + cf] * sF, Wsrc[(2*m+1) * NG + cf] * sF);
        wG[m] = pack2(Wsrc[(2*m) * NG + cg] * sG, Wsrc[(2*m+1) * NG + cg] * sG);
        wO[m] = pack2(Wsrc[(2*m) * NG + co] * sO, Wsrc[(2*m+1) * NG + co] * sO);
    }
    // bias folded once into the x-group accumulator init
    const u64 bI2 = pack2((half == 0) ? bias[ci] * sI : 0.f, 0.f);
    const u64 bF2 = pack2((half == 0) ? bias[cf] * sF : 0.f, 0.f);
    const u64 bG2 = pack2((half == 0) ? bias[cg] * sG : 0.f, 0.f);
    const u64 bO2 = pack2((half == 0) ? bias[co] * sO : 0.f, 0.f);

    // cp.async: lanes 0-15 fetch 16 x 16B = 4 elems x 16 floats per step
    const float* xsrc = x + (size_t)(e0 + (lane >> 2)) * (NT * ND) + (lane & 3) * 4;
    const u32 xdst0 = smem_u32(&xsm[0][wib][lane >> 2][(lane & 3) * 4]);

    // per-lane operand read base (buffer 0): x-group reads xsm, h-group hsm
    const u32 rbase = (half == 0) ? smem_u32(&xsm[0][wib][0][0])
                                  : smem_u32(&hsm[0][wib][0][0]);
    const u32 BUFSTR = 4 * 4 * 16 * 4;   // 1024 B between buffers

    // h write base: low lanes own elems 0,1; high lanes own elems 2,3
    float* hw0 = &hsm[0][wib][half * 2 + 0][j];
    float* hw1 = &hsm[0][wib][half * 2 + 1][j];
    const int HBUF = 4 * 4 * 16;         // floats between buffers

    // init h = 0 in buffer 0; prefetch x(t=0)
    *hw0 = 0.f;
    *hw1 = 0.f;
    if (half == 0) {
        asm volatile("cp.async.ca.shared.global [%0], [%1], 16;"
                     :: "r"(xdst0), "l"(xsrc) : "memory");
    }
    asm volatile("cp.async.commit_group;" ::: "memory");

    // states: each lane owns 2 elements (P,Q) = (A,B) on low, (C,D) on high
    float cP = 0.f, cQ = 0.f;

#pragma unroll 1
    for (int t = 0; t < NT; ++t) {
        const int b  = t & 1;
        const int b1 = b ^ 1;

        // prefetch x(t+1) into the other buffer (clamped on last iter)
        {
            int t1 = (t + 1 < NT) ? (t + 1) : (NT - 1);
            if (half == 0) {
                asm volatile("cp.async.ca.shared.global [%0], [%1], 16;"
                             :: "r"(xdst0 + (u32)(b1 * BUFSTR)),
                                "l"(xsrc + (size_t)t1 * ND) : "memory");
            }
            asm volatile("cp.async.commit_group;" ::: "memory");
        }
        asm volatile("cp.async.wait_group 1;" ::: "memory");
        __syncwarp();   // orders prev-step h STS before this step's LDS

        // accumulate partial z for all 4 elements
        const u32 rb = rbase + (u32)(b * BUFSTR);
        u64 aI[4], aF[4], aG[4], aO[4];
#pragma unroll
        for (int e = 0; e < 4; ++e) {
            u64 q0, q1, q2, q3, q4, q5, q6, q7;
            lds_v2u64(q0, q1, rb + e * 64 + 0);
            lds_v2u64(q2, q3, rb + e * 64 + 16);
            lds_v2u64(q4, q5, rb + e * 64 + 32);
            lds_v2u64(q6, q7, rb + e * 64 + 48);
            u64 i_ = bI2, f_ = bF2, g_ = bG2, o_ = bO2;
            i_ = ffma2(q0, wI[0], i_); f_ = ffma2(q0, wF[0], f_);
            g_ = ffma2(q0, wG[0], g_); o_ = ffma2(q0, wO[0], o_);
            i_ = ffma2(q1, wI[1], i_); f_ = ffma2(q1, wF[1], f_);
            g_ = ffma2(q1, wG[1], g_); o_ = ffma2(q1, wO[1], o_);
            i_ = ffma2(q2, wI[2], i_); f_ = ffma2(q2, wF[2], f_);
            g_ = ffma2(q2, wG[2], g_); o_ = ffma2(q2, wO[2], o_);
            i_ = ffma2(q3, wI[3], i_); f_ = ffma2(q3, wF[3], f_);
            g_ = ffma2(q3, wG[3], g_); o_ = ffma2(q3, wO[3], o_);
            i_ = ffma2(q4, wI[4], i_); f_ = ffma2(q4, wF[4], f_);
            g_ = ffma2(q4, wG[4], g_); o_ = ffma2(q4, wO[4], o_);
            i_ = ffma2(q5, wI[5], i_); f_ = ffma2(q5, wF[5], f_);
            g_ = ffma2(q5, wG[5], g_); o_ = ffma2(q5, wO[5], o_);
            i_ = ffma2(q6, wI[6], i_); f_ = ffma2(q6, wF[6], f_);
            g_ = ffma2(q6, wG[6], g_); o_ = ffma2(q6, wO[6], o_);
            i_ = ffma2(q7, wI[7], i_); f_ = ffma2(q7, wF[7], f_);
            g_ = ffma2(q7, wG[7], g_); o_ = ffma2(q7, wO[7], o_);
            aI[e] = i_; aF[e] = f_; aG[e] = g_; aO[e] = o_;
        }

        // lo+hi reduce the k-pairs
        float zpI[4], zpF[4], zpG[4], zpO[4];
#pragma unroll
        for (int e = 0; e < 4; ++e) {
            float lo, hi;
            unpack2(aI[e], lo, hi); zpI[e] = lo + hi;
            unpack2(aF[e], lo, hi); zpF[e] = lo + hi;
            unpack2(aG[e], lo, hi); zpG[e] = lo + hi;
            unpack2(aO[e], lo, hi); zpO[e] = lo + hi;
        }

        // exchange: low lanes send x-partials of C,D; high lanes send
        // h-partials of A,B. After this, low lanes hold full z of A,B (P,Q),
        // high lanes hold full z of C,D.
        const int sP = half ? 0 : 2;   // index of first element to SEND
        float rI0 = __shfl_xor_sync(0xffffffffu, zpI[sP],     16);
        float rI1 = __shfl_xor_sync(0xffffffffu, zpI[sP + 1], 16);
        float rF0 = __shfl_xor_sync(0xffffffffu, zpF[sP],     16);
        float rF1 = __shfl_xor_sync(0xffffffffu, zpF[sP + 1], 16);
        float rG0 = __shfl_xor_sync(0xffffffffu, zpG[sP],     16);
        float rG1 = __shfl_xor_sync(0xffffffffu, zpG[sP + 1], 16);
        float rO0 = __shfl_xor_sync(0xffffffffu, zpO[sP],     16);
        float rO1 = __shfl_xor_sync(0xffffffffu, zpO[sP + 1], 16);
        const int kP = half ? 2 : 0;   // index of first element KEPT locally
        float zI_P = zpI[kP] + rI0,     zI_Q = zpI[kP + 1] + rI1;
        float zF_P = zpF[kP] + rF0,     zF_Q = zpF[kP + 1] + rF1;
        float zG_P = zpG[kP] + rG0,     zG_Q = zpG[kP + 1] + rG1;
        float zO_P = zpO[kP] + rO0,     zO_Q = zpO[kP + 1] + rO1;

        // two independent recurrence chains per lane
        float vI_P = fmaf(0.5f, tanhap(zI_P), 0.5f);
        float vI_Q = fmaf(0.5f, tanhap(zI_Q), 0.5f);
        float vF_P = fmaf(0.5f, tanhap(zF_P), 0.5f);
        float vF_Q = fmaf(0.5f, tanhap(zF_Q), 0.5f);
        float vG_P = tanhap(zG_P);
        float vG_Q = tanhap(zG_Q);
        float vO_P = fmaf(0.5f, tanhap(zO_P), 0.5f);
        float vO_Q = fmaf(0.5f, tanhap(zO_Q), 0.5f);
        cP = fmaf(vF_P, cP, vI_P * vG_P);
        cQ = fmaf(vF_Q, cQ, vI_Q * vG_Q);
        float hP = vO_P * tanhap(cP);
        float hQ = vO_Q * tanhap(cQ);

        // publish h(t+1) into the other buffer
        hw0[b1 * HBUF] = hP;
        hw1[b1 * HBUF] = hQ;
    }

    // head: logits = c_T @ Wd + bd, softmax over 2 classes.
    // low lanes hold cA,cB; high lanes hold cC,cD. Reduce within each half.
    const float L2E = 1.44269504088896340736f;
    const float wd0 = Wd[2 * j], wd1 = Wd[2 * j + 1];
    float pP0 = cP * wd0, pP1 = cP * wd1;
    float pQ0 = cQ * wd0, pQ1 = cQ * wd1;
#pragma unroll
    for (int off = 8; off; off >>= 1) {
        pP0 += __shfl_xor_sync(0xffffffffu, pP0, off, 16);
        pP1 += __shfl_xor_sync(0xffffffffu, pP1, off, 16);
        pQ0 += __shfl_xor_sync(0xffffffffu, pQ0, off, 16);
        pQ1 += __shfl_xor_sync(0xffffffffu, pQ1, off, 16);
    }
    if (j == 0) {
        const int eP = e0 + half * 2;     // low: A, high: C
        const float b0 = bd[0], b1v = bd[1];
        {
            float l0 = pP0 + b0, l1 = pP1 + b1v;
            float mx = fmaxf(l0, l1);
            float q0 = ex2f((l0 - mx) * L2E);
            float q1 = ex2f((l1 - mx) * L2E);
            float inv = rcpf(q0 + q1);
            out[2 * eP]     = q0 * inv;
            out[2 * eP + 1] = q1 * inv;
        }
        {
            float l0 = pQ0 + b0, l1 = pQ1 + b1v;
            float mx = fmaxf(l0, l1);
            float q0 = ex2f((l0 - mx) * L2E);
            float q1 = ex2f((l1 - mx) * L2E);
            float inv = rcpf(q0 + q1);
            out[2 * (eP + 1)]     = q0 * inv;
            out[2 * (eP + 1) + 1] = q1 * inv;
        }
    }
}

extern "C" void kernel_launch(void* const* d_in, const int* in_sizes, int n_in,
                              void* d_out, int out_size)
{
    const float* x  = (const float*)d_in[0];
    const float* Wi = (const float*)d_in[1];
    const float* Wh = (const float*)d_in[2];
    const float* b  = (const float*)d_in[3];
    const float* Wd = (const float*)d_in[4];
    const float* bd = (const float*)d_in[5];
    float* out = (float*)d_out;

    lstm_fused_kernel<<<NB / 16, 128>>>(x, Wi, Wh, b, Wd, bd, out);
}

// round 9
// speedup vs baseline: 1.0011x; 1.0011x over previous
#include <cuda_runtime.h>
#include <cstdint>

// CarryLSTMModel: B=8192, T=1024, D=16, H=16 (4H=64 gates, order i,f,g,o)
// Split-K, 4 elements per warp (A,B,C,D):
//   lanes 0-15  hold Wi (x-part) weights for gate cols {j,j+16,j+32,j+48},
//   lanes 16-31 hold Wh (h-part) weights for the same cols.
// Each lane computes partial z for ALL 4 elements (128 FFMA2/warp-step).
// shfl_xor(16) combines partials AND redistributes: low lanes finalize A,B;
// high lanes finalize C,D -> every lane runs TWO independent recurrence
// chains (ILP in the serial tail). Weights shared across elements: 64 regs.
// Operands loaded as ld.shared.v2.u64 (no pack movs). x staged via cp.async.
// Activations: MUFU.TANH, sig(z)=0.5+0.5*tanh(z/2) (weights pre-scaled).

#define NB 8192
#define NT 1024
#define ND 16
#define NG 64

typedef unsigned long long u64;
typedef unsigned int u32;

__device__ __forceinline__ u64 pack2(float lo, float hi) {
    u64 r;
    asm("mov.b64 %0, {%1, %2};" : "=l"(r) : "r"(__float_as_uint(lo)), "r"(__float_as_uint(hi)));
    return r;
}
__device__ __forceinline__ void unpack2(u64 v, float& lo, float& hi) {
    u32 a, b;
    asm("mov.b64 {%0, %1}, %2;" : "=r"(a), "=r"(b) : "l"(v));
    lo = __uint_as_float(a);
    hi = __uint_as_float(b);
}
__device__ __forceinline__ u64 ffma2(u64 a, u64 b, u64 c) {
    u64 d;
    asm("fma.rn.f32x2 %0, %1, %2, %3;" : "=l"(d) : "l"(a), "l"(b), "l"(c));
    return d;
}
__device__ __forceinline__ float tanhap(float x) {
    float r; asm("tanh.approx.f32 %0, %1;" : "=f"(r) : "f"(x)); return r;
}
__device__ __forceinline__ float ex2f(float x) {
    float r; asm("ex2.approx.f32 %0, %1;" : "=f"(r) : "f"(x)); return r;
}
__device__ __forceinline__ float rcpf(float x) {
    float r; asm("rcp.approx.f32 %0, %1;" : "=f"(r) : "f"(x)); return r;
}
__device__ __forceinline__ u32 smem_u32(const void* p) {
    return (u32)__cvta_generic_to_shared(p);
}
__device__ __forceinline__ void lds_v2u64(u64& a, u64& b, u32 addr) {
    asm volatile("ld.shared.v2.u64 {%0, %1}, [%2];" : "=l"(a), "=l"(b) : "r"(addr));
}

__global__ __launch_bounds__(128, 3)
void lstm_fused_kernel(const float* __restrict__ x,
                       const float* __restrict__ Wi,
                       const float* __restrict__ Wh,
                       const float* __restrict__ bias,
                       const float* __restrict__ Wd,
                       const float* __restrict__ bd,
                       float* __restrict__ out)
{
    // staging, identical shapes so stride math is shared:
    // xsm[buf][warp][elem(4)][k(16)], hsm likewise. 2 KB each.
    __shared__ float xsm[2][4][4][16];
    __shared__ float hsm[2][4][4][16];

    const int wib  = threadIdx.x >> 5;
    const int lane = threadIdx.x & 31;
    const int half = lane >> 4;      // 0 = x-group (Wi), 1 = h-group (Wh)
    const int j    = lane & 15;      // gate index / hidden index
    const int e0   = blockIdx.x * 16 + wib * 4;   // elements A..D = e0..e0+3

    // sig(z) = 0.5 + 0.5*tanh(z/2): weights/bias pre-scaled so z is the tanh arg.
    const float sI = 0.5f, sF = 0.5f, sG = 1.0f, sO = 0.5f;
    const int ci = j, cf = j + 16, cg = j + 32, co = j + 48;

    const float* Wsrc = (half == 0) ? Wi : Wh;
    u64 wI[8], wF[8], wG[8], wO[8];
#pragma unroll
    for (int m = 0; m < 8; ++m) {
        wI[m] = pack2(Wsrc[(2*m) * NG + ci] * sI, Wsrc[(2*m+1) * NG + ci] * sI);
        wF[m] = pack2(Wsrc[(2*m) * NG + cf] * sF, Wsrc[(2*m+1) * NG + cf] * sF);
        wG[m] = pack2(Wsrc[(2*m) * NG + cg] * sG, Wsrc[(2*m+1) * NG + cg] * sG);
        wO[m] = pack2(Wsrc[(2*m) * NG + co] * sO, Wsrc[(2*m+1) * NG + co] * sO);
    }
    // bias folded once into the x-group accumulator init
    const u64 bI2 = pack2((half == 0) ? bias[ci] * sI : 0.f, 0.f);
    const u64 bF2 = pack2((half == 0) ? bias[cf] * sF : 0.f, 0.f);
    const u64 bG2 = pack2((half == 0) ? bias[cg] * sG : 0.f, 0.f);
    const u64 bO2 = pack2((half == 0) ? bias[co] * sO : 0.f, 0.f);

    // cp.async: lanes 0-15 fetch 16 x 16B = 4 elems x 16 floats per step
    const float* xsrc = x + (size_t)(e0 + (lane >> 2)) * (NT * ND) + (lane & 3) * 4;
    const u32 xdst0 = smem_u32(&xsm[0][wib][lane >> 2][(lane & 3) * 4]);

    // per-lane operand read base (buffer 0): x-group reads xsm, h-group hsm
    const u32 rbase = (half == 0) ? smem_u32(&xsm[0][wib][0][0])
                                  : smem_u32(&hsm[0][wib][0][0]);
    const u32 BUFSTR = 4 * 4 * 16 * 4;   // 1024 B between buffers

    // h write base: low lanes own elems 0,1; high lanes own elems 2,3
    float* hw0 = &hsm[0][wib][half * 2 + 0][j];
    float* hw1 = &hsm[0][wib][half * 2 + 1][j];
    const int HBUF = 4 * 4 * 16;         // floats between buffers

    // init h = 0 in buffer 0; prefetch x(t=0)
    *hw0 = 0.f;
    *hw1 = 0.f;
    if (half == 0) {
        asm volatile("cp.async.ca.shared.global [%0], [%1], 16;"
                     :: "r"(xdst0), "l"(xsrc) : "memory");
    }
    asm volatile("cp.async.commit_group;" ::: "memory");

    // states: each lane owns 2 elements (P,Q) = (A,B) on low, (C,D) on high
    float cP = 0.f, cQ = 0.f;

#pragma unroll 1
    for (int t = 0; t < NT; ++t) {
        const int b  = t & 1;
        const int b1 = b ^ 1;

        // prefetch x(t+1) into the other buffer (clamped on last iter)
        {
            int t1 = (t + 1 < NT) ? (t + 1) : (NT - 1);
            if (half == 0) {
                asm volatile("cp.async.ca.shared.global [%0], [%1], 16;"
                             :: "r"(xdst0 + (u32)(b1 * BUFSTR)),
                                "l"(xsrc + (size_t)t1 * ND) : "memory");
            }
            asm volatile("cp.async.commit_group;" ::: "memory");
        }
        asm volatile("cp.async.wait_group 1;" ::: "memory");
        __syncwarp();   // orders prev-step h STS before this step's LDS

        // accumulate partial z for all 4 elements
        const u32 rb = rbase + (u32)(b * BUFSTR);
        u64 aI[4], aF[4], aG[4], aO[4];
#pragma unroll
        for (int e = 0; e < 4; ++e) {
            u64 q0, q1, q2, q3, q4, q5, q6, q7;
            lds_v2u64(q0, q1, rb + e * 64 + 0);
            lds_v2u64(q2, q3, rb + e * 64 + 16);
            lds_v2u64(q4, q5, rb + e * 64 + 32);
            lds_v2u64(q6, q7, rb + e * 64 + 48);
            u64 i_ = bI2, f_ = bF2, g_ = bG2, o_ = bO2;
            i_ = ffma2(q0, wI[0], i_); f_ = ffma2(q0, wF[0], f_);
            g_ = ffma2(q0, wG[0], g_); o_ = ffma2(q0, wO[0], o_);
            i_ = ffma2(q1, wI[1], i_); f_ = ffma2(q1, wF[1], f_);
            g_ = ffma2(q1, wG[1], g_); o_ = ffma2(q1, wO[1], o_);
            i_ = ffma2(q2, wI[2], i_); f_ = ffma2(q2, wF[2], f_);
            g_ = ffma2(q2, wG[2], g_); o_ = ffma2(q2, wO[2], o_);
            i_ = ffma2(q3, wI[3], i_); f_ = ffma2(q3, wF[3], f_);
            g_ = ffma2(q3, wG[3], g_); o_ = ffma2(q3, wO[3], o_);
            i_ = ffma2(q4, wI[4], i_); f_ = ffma2(q4, wF[4], f_);
            g_ = ffma2(q4, wG[4], g_); o_ = ffma2(q4, wO[4], o_);
            i_ = ffma2(q5, wI[5], i_); f_ = ffma2(q5, wF[5], f_);
            g_ = ffma2(q5, wG[5], g_); o_ = ffma2(q5, wO[5], o_);
            i_ = ffma2(q6, wI[6], i_); f_ = ffma2(q6, wF[6], f_);
            g_ = ffma2(q6, wG[6], g_); o_ = ffma2(q6, wO[6], o_);
            i_ = ffma2(q7, wI[7], i_); f_ = ffma2(q7, wF[7], f_);
            g_ = ffma2(q7, wG[7], g_); o_ = ffma2(q7, wO[7], o_);
            aI[e] = i_; aF[e] = f_; aG[e] = g_; aO[e] = o_;
        }

        // lo+hi reduce the k-pairs
        float zpI[4], zpF[4], zpG[4], zpO[4];
#pragma unroll
        for (int e = 0; e < 4; ++e) {
            float lo, hi;
            unpack2(aI[e], lo, hi); zpI[e] = lo + hi;
            unpack2(aF[e], lo, hi); zpF[e] = lo + hi;
            unpack2(aG[e], lo, hi); zpG[e] = lo + hi;
            unpack2(aO[e], lo, hi); zpO[e] = lo + hi;
        }

        // exchange: low lanes send x-partials of C,D; high lanes send
        // h-partials of A,B. After this, low lanes hold full z of A,B (P,Q),
        // high lanes hold full z of C,D.
        const int sP = half ? 0 : 2;   // index of first element to SEND
        float rI0 = __shfl_xor_sync(0xffffffffu, zpI[sP],     16);
        float rI1 = __shfl_xor_sync(0xffffffffu, zpI[sP + 1], 16);
        float rF0 = __shfl_xor_sync(0xffffffffu, zpF[sP],     16);
        float rF1 = __shfl_xor_sync(0xffffffffu, zpF[sP + 1], 16);
        float rG0 = __shfl_xor_sync(0xffffffffu, zpG[sP],     16);
        float rG1 = __shfl_xor_sync(0xffffffffu, zpG[sP + 1], 16);
        float rO0 = __shfl_xor_sync(0xffffffffu, zpO[sP],     16);
        float rO1 = __shfl_xor_sync(0xffffffffu, zpO[sP + 1], 16);
        const int kP = half ? 2 : 0;   // index of first element KEPT locally
        float zI_P = zpI[kP] + rI0,     zI_Q = zpI[kP + 1] + rI1;
        float zF_P = zpF[kP] + rF0,     zF_Q = zpF[kP + 1] + rF1;
        float zG_P = zpG[kP] + rG0,     zG_Q = zpG[kP + 1] + rG1;
        float zO_P = zpO[kP] + rO0,     zO_Q = zpO[kP + 1] + rO1;

        // two independent recurrence chains per lane
        float vI_P = fmaf(0.5f, tanhap(zI_P), 0.5f);
        float vI_Q = fmaf(0.5f, tanhap(zI_Q), 0.5f);
        float vF_P = fmaf(0.5f, tanhap(zF_P), 0.5f);
        float vF_Q = fmaf(0.5f, tanhap(zF_Q), 0.5f);
        float vG_P = tanhap(zG_P);
        float vG_Q = tanhap(zG_Q);
        float vO_P = fmaf(0.5f, tanhap(zO_P), 0.5f);
        float vO_Q = fmaf(0.5f, tanhap(zO_Q), 0.5f);
        cP = fmaf(vF_P, cP, vI_P * vG_P);
        cQ = fmaf(vF_Q, cQ, vI_Q * vG_Q);
        float hP = vO_P * tanhap(cP);
        float hQ = vO_Q * tanhap(cQ);

        // publish h(t+1) into the other buffer
        hw0[b1 * HBUF] = hP;
        hw1[b1 * HBUF] = hQ;
    }

    // head: logits = c_T @ Wd + bd, softmax over 2 classes.
    // low lanes hold cA,cB; high lanes hold cC,cD. Reduce within each half.
    const float L2E = 1.44269504088896340736f;
    const float wd0 = Wd[2 * j], wd1 = Wd[2 * j + 1];
    float pP0 = cP * wd0, pP1 = cP * wd1;
    float pQ0 = cQ * wd0, pQ1 = cQ * wd1;
#pragma unroll
    for (int off = 8; off; off >>= 1) {
        pP0 += __shfl_xor_sync(0xffffffffu, pP0, off, 16);
        pP1 += __shfl_xor_sync(0xffffffffu, pP1, off, 16);
        pQ0 += __shfl_xor_sync(0xffffffffu, pQ0, off, 16);
        pQ1 += __shfl_xor_sync(0xffffffffu, pQ1, off, 16);
    }
    if (j == 0) {
        const int eP = e0 + half * 2;     // low: A, high: C
        const float b0 = bd[0], b1v = bd[1];
        {
            float l0 = pP0 + b0, l1 = pP1 + b1v;
            float mx = fmaxf(l0, l1);
            float q0 = ex2f((l0 - mx) * L2E);
            float q1 = ex2f((l1 - mx) * L2E);
            float inv = rcpf(q0 + q1);
            out[2 * eP]     = q0 * inv;
            out[2 * eP + 1] = q1 * inv;
        }
        {
            float l0 = pQ0 + b0, l1 = pQ1 + b1v;
            float mx = fmaxf(l0, l1);
            float q0 = ex2f((l0 - mx) * L2E);
            float q1 = ex2f((l1 - mx) * L2E);
            float inv = rcpf(q0 + q1);
            out[2 * (eP + 1)]     = q0 * inv;
            out[2 * (eP + 1) + 1] = q1 * inv;
        }
    }
}

extern "C" void kernel_launch(void* const* d_in, const int* in_sizes, int n_in,
                              void* d_out, int out_size)
{
    const float* x  = (const float*)d_in[0];
    const float* Wi = (const float*)d_in[1];
    const float* Wh = (const float*)d_in[2];
    const float* b  = (const float*)d_in[3];
    const float* Wd = (const float*)d_in[4];
    const float* bd = (const float*)d_in[5];
    float* out = (float*)d_out;

    lstm_fused_kernel<<<NB / 16, 128>>>(x, Wi, Wh, b, Wd, bd, out);
}

// round 10
// speedup vs baseline: 1.0581x; 1.0570x over previous
#include <cuda_runtime.h>
#include <cstdint>

// CarryLSTMModel: B=8192, T=1024, D=16, H=16 (4H=64 gates, order i,f,g,o)
// Split-K layout (R7) tightened for 4 CTAs/SM:
//   1 warp = 2 batch elements (A, B).
//   lanes 0-15  hold Wi (x-part) weights for gate cols {j,j+16,j+32,j+48},
//   lanes 16-31 hold Wh (h-part) weights for the same cols.
// Same FFMA2 instructions serve both roles -> 64 weight regs total.
// One shfl_xor(16) per gate merges partials and redistributes: elem A's z on
// low lanes, elem B's on high lanes -> activations at full lane density.
// Operands loaded straight into packed u64 via ld.shared.v2.u64 (no MOV packs).
// x staged via cp.async double-buffer; h via double-buffered smem.
// Activations: MUFU.TANH, sig(z)=0.5+0.5*tanh(z/2) (weights pre-scaled).

#define NB 8192
#define NT 1024
#define ND 16
#define NG 64

typedef unsigned long long u64;
typedef unsigned int u32;

__device__ __forceinline__ u64 pack2(float lo, float hi) {
    u64 r;
    asm("mov.b64 %0, {%1, %2};" : "=l"(r) : "r"(__float_as_uint(lo)), "r"(__float_as_uint(hi)));
    return r;
}
__device__ __forceinline__ void unpack2(u64 v, float& lo, float& hi) {
    u32 a, b;
    asm("mov.b64 {%0, %1}, %2;" : "=r"(a), "=r"(b) : "l"(v));
    lo = __uint_as_float(a);
    hi = __uint_as_float(b);
}
__device__ __forceinline__ u64 ffma2(u64 a, u64 b, u64 c) {
    u64 d;
    asm("fma.rn.f32x2 %0, %1, %2, %3;" : "=l"(d) : "l"(a), "l"(b), "l"(c));
    return d;
}
__device__ __forceinline__ float tanhap(float x) {
    float r; asm("tanh.approx.f32 %0, %1;" : "=f"(r) : "f"(x)); return r;
}
__device__ __forceinline__ float ex2f(float x) {
    float r; asm("ex2.approx.f32 %0, %1;" : "=f"(r) : "f"(x)); return r;
}
__device__ __forceinline__ float rcpf(float x) {
    float r; asm("rcp.approx.f32 %0, %1;" : "=f"(r) : "f"(x)); return r;
}
__device__ __forceinline__ u32 smem_u32(const void* p) {
    return (u32)__cvta_generic_to_shared(p);
}
__device__ __forceinline__ void lds_v2u64(u64& a, u64& b, u32 addr) {
    asm volatile("ld.shared.v2.u64 {%0, %1}, [%2];" : "=l"(a), "=l"(b) : "r"(addr));
}

__global__ __launch_bounds__(128, 4)
void lstm_fused_kernel(const float* __restrict__ x,
                       const float* __restrict__ Wi,
                       const float* __restrict__ Wh,
                       const float* __restrict__ bias,
                       const float* __restrict__ Wd,
                       const float* __restrict__ bd,
                       float* __restrict__ out)
{
    // identical [buf][warp][elem(2)][k(16)] layout for x and h -> shared offsets
    __shared__ float xsm[2][4][2][16];   // 1 KB
    __shared__ float hsm[2][4][2][16];   // 1 KB

    const int wib  = threadIdx.x >> 5;
    const int lane = threadIdx.x & 31;
    const int half = lane >> 4;      // 0 = x-group (Wi), 1 = h-group (Wh)
    const int j    = lane & 15;      // gate index / hidden index
    const int e0   = blockIdx.x * 8 + wib * 2;   // warp's element A; B = e0+1

    // sig(z) = 0.5 + 0.5*tanh(z/2): weights/bias pre-scaled so z is the tanh arg.
    const float sI = 0.5f, sF = 0.5f, sG = 1.0f, sO = 0.5f;
    const int ci = j, cf = j + 16, cg = j + 32, co = j + 48;

    const float* Wsrc = (half == 0) ? Wi : Wh;
    u64 wI[8], wF[8], wG[8], wO[8];
#pragma unroll
    for (int m = 0; m < 8; ++m) {
        wI[m] = pack2(Wsrc[(2*m) * NG + ci] * sI, Wsrc[(2*m+1) * NG + ci] * sI);
        wF[m] = pack2(Wsrc[(2*m) * NG + cf] * sF, Wsrc[(2*m+1) * NG + cf] * sF);
        wG[m] = pack2(Wsrc[(2*m) * NG + cg] * sG, Wsrc[(2*m+1) * NG + cg] * sG);
        wO[m] = pack2(Wsrc[(2*m) * NG + co] * sO, Wsrc[(2*m+1) * NG + co] * sO);
    }
    // bias folded once into the x-group accumulator init
    const u64 bI2 = pack2((half == 0) ? bias[ci] * sI : 0.f, 0.f);
    const u64 bF2 = pack2((half == 0) ? bias[cf] * sF : 0.f, 0.f);
    const u64 bG2 = pack2((half == 0) ? bias[cg] * sG : 0.f, 0.f);
    const u64 bO2 = pack2((half == 0) ? bias[co] * sO : 0.f, 0.f);

    // cp.async: lanes 0-7 fetch 8 x 16B = 2 elems x 16 floats per step
    const float* xsrc = x + (size_t)(e0 + ((lane >> 2) & 1)) * (NT * ND) + (lane & 3) * 4;
    const u32 xdst0 = smem_u32(&xsm[0][wib][(lane >> 2) & 1][(lane & 3) * 4]);

    // per-lane operand read base (buffer 0): x-group reads xsm, h-group hsm
    const u32 rbase = (half == 0) ? smem_u32(&xsm[0][wib][0][0])
                                  : smem_u32(&hsm[0][wib][0][0]);
    const u32 BUFSTR = 4 * 2 * 16 * 4;   // 512 B between buffers

    // h write slot: elem A's h from low lanes, elem B's from high lanes
    float* hw = &hsm[0][wib][half][j];
    const int HBUF = 4 * 2 * 16;         // floats between buffers

    // init h = 0 (buffer 0); prefetch x(t=0) into buffer 0
    *hw = 0.f;
    if (lane < 8) {
        asm volatile("cp.async.ca.shared.global [%0], [%1], 16;"
                     :: "r"(xdst0), "l"(xsrc) : "memory");
    }
    asm volatile("cp.async.commit_group;" ::: "memory");

    float c = 0.f;    // cell state: elem A on low lanes, elem B on high lanes
    float hv = 0.f;   // hidden state, same split

#pragma unroll 1
    for (int t = 0; t < NT; ++t) {
        const int b  = t & 1;
        const int b1 = b ^ 1;

        // prefetch x(t+1) into the other buffer (clamped on last iter)
        {
            int t1 = (t + 1 < NT) ? (t + 1) : (NT - 1);
            if (lane < 8) {
                asm volatile("cp.async.ca.shared.global [%0], [%1], 16;"
                             :: "r"(xdst0 + (u32)(b1 * BUFSTR)),
                                "l"(xsrc + (size_t)t1 * ND) : "memory");
            }
            asm volatile("cp.async.commit_group;" ::: "memory");
        }
        asm volatile("cp.async.wait_group 1;" ::: "memory");
        __syncwarp();   // orders prev-step h STS before this step's LDS

        // operand stream straight into packed u64 (x-group: x of A,B;
        // h-group: h of A,B — same offsets, different base)
        const u32 rb = rbase + (u32)(b * BUFSTR);
        u64 qA0, qA1, qA2, qA3, qA4, qA5, qA6, qA7;
        u64 qB0, qB1, qB2, qB3, qB4, qB5, qB6, qB7;
        lds_v2u64(qA0, qA1, rb + 0);
        lds_v2u64(qA2, qA3, rb + 16);
        lds_v2u64(qA4, qA5, rb + 32);
        lds_v2u64(qA6, qA7, rb + 48);
        lds_v2u64(qB0, qB1, rb + 64);
        lds_v2u64(qB2, qB3, rb + 80);
        lds_v2u64(qB4, qB5, rb + 96);
        lds_v2u64(qB6, qB7, rb + 112);

        // partial z accumulation (x-part on low lanes, h-part on high lanes)
        u64 aI = bI2, aF = bF2, aG = bG2, aO = bO2;   // elem A
        u64 eI = bI2, eF = bF2, eG = bG2, eO = bO2;   // elem B
        aI = ffma2(qA0, wI[0], aI); aF = ffma2(qA0, wF[0], aF);
        aG = ffma2(qA0, wG[0], aG); aO = ffma2(qA0, wO[0], aO);
        eI = ffma2(qB0, wI[0], eI); eF = ffma2(qB0, wF[0], eF);
        eG = ffma2(qB0, wG[0], eG); eO = ffma2(qB0, wO[0], eO);
        aI = ffma2(qA1, wI[1], aI); aF = ffma2(qA1, wF[1], aF);
        aG = ffma2(qA1, wG[1], aG); aO = ffma2(qA1, wO[1], aO);
        eI = ffma2(qB1, wI[1], eI); eF = ffma2(qB1, wF[1], eF);
        eG = ffma2(qB1, wG[1], eG); eO = ffma2(qB1, wO[1], eO);
        aI = ffma2(qA2, wI[2], aI); aF = ffma2(qA2, wF[2], aF);
        aG = ffma2(qA2, wG[2], aG); aO = ffma2(qA2, wO[2], aO);
        eI = ffma2(qB2, wI[2], eI); eF = ffma2(qB2, wF[2], eF);
        eG = ffma2(qB2, wG[2], eG); eO = ffma2(qB2, wO[2], eO);
        aI = ffma2(qA3, wI[3], aI); aF = ffma2(qA3, wF[3], aF);
        aG = ffma2(qA3, wG[3], aG); aO = ffma2(qA3, wO[3], aO);
        eI = ffma2(qB3, wI[3], eI); eF = ffma2(qB3, wF[3], eF);
        eG = ffma2(qB3, wG[3], eG); eO = ffma2(qB3, wO[3], eO);
        aI = ffma2(qA4, wI[4], aI); aF = ffma2(qA4, wF[4], aF);
        aG = ffma2(qA4, wG[4], aG); aO = ffma2(qA4, wO[4], aO);
        eI = ffma2(qB4, wI[4], eI); eF = ffma2(qB4, wF[4], eF);
        eG = ffma2(qB4, wG[4], eG); eO = ffma2(qB4, wO[4], eO);
        aI = ffma2(qA5, wI[5], aI); aF = ffma2(qA5, wF[5], aF);
        aG = ffma2(qA5, wG[5], aG); aO = ffma2(qA5, wO[5], aO);
        eI = ffma2(qB5, wI[5], eI); eF = ffma2(qB5, wF[5], eF);
        eG = ffma2(qB5, wG[5], eG); eO = ffma2(qB5, wO[5], eO);
        aI = ffma2(qA6, wI[6], aI); aF = ffma2(qA6, wF[6], aF);
        aG = ffma2(qA6, wG[6], aG); aO = ffma2(qA6, wO[6], aO);
        eI = ffma2(qB6, wI[6], eI); eF = ffma2(qB6, wF[6], eF);
        eG = ffma2(qB6, wG[6], eG); eO = ffma2(qB6, wO[6], eO);
        aI = ffma2(qA7, wI[7], aI); aF = ffma2(qA7, wF[7], aF);
        aG = ffma2(qA7, wG[7], aG); aO = ffma2(qA7, wO[7], aO);
        eI = ffma2(qB7, wI[7], eI); eF = ffma2(qB7, wF[7], eF);
        eG = ffma2(qB7, wG[7], eG); eO = ffma2(qB7, wO[7], eO);

        float lo, hi;
        float zIA, zFA, zGA, zOA, zIB, zFB, zGB, zOB;
        unpack2(aI, lo, hi); zIA = lo + hi;
        unpack2(aF, lo, hi); zFA = lo + hi;
        unpack2(aG, lo, hi); zGA = lo + hi;
        unpack2(aO, lo, hi); zOA = lo + hi;
        unpack2(eI, lo, hi); zIB = lo + hi;
        unpack2(eF, lo, hi); zFB = lo + hi;
        unpack2(eG, lo, hi); zGB = lo + hi;
        unpack2(eO, lo, hi); zOB = lo + hi;

        // combine halves + redistribute: low lanes end with elem A's z,
        // high lanes with elem B's z. Send the "other element's" partial.
        float sI_ = half ? zIA : zIB;
        float sF_ = half ? zFA : zFB;
        float sG_ = half ? zGA : zGB;
        float sO_ = half ? zOA : zOB;
        float rI = __shfl_xor_sync(0xffffffffu, sI_, 16);
        float rF = __shfl_xor_sync(0xffffffffu, sF_, 16);
        float rG = __shfl_xor_sync(0xffffffffu, sG_, 16);
        float rO = __shfl_xor_sync(0xffffffffu, sO_, 16);
        float zI = (half ? zIB : zIA) + rI;
        float zF = (half ? zFB : zFA) + rF;
        float zG = (half ? zGB : zGA) + rG;
        float zO = (half ? zOB : zOA) + rO;

        // activations at full lane density
        float vI = fmaf(0.5f, tanhap(zI), 0.5f);   // sig
        float vF = fmaf(0.5f, tanhap(zF), 0.5f);   // sig
        float vG = tanhap(zG);                     // tanh
        float vO = fmaf(0.5f, tanhap(zO), 0.5f);   // sig
        c  = fmaf(vF, c, vI * vG);
        hv = vO * tanhap(c);

        // publish h(t+1): [elem half][j]
        hw[b1 * HBUF] = hv;
    }

    // head: logits = c_T @ Wd + bd, softmax over 2 classes.
    // low lanes hold cA, high lanes cB — reduce each half independently.
    const float L2E = 1.44269504088896340736f;
    float p0 = c * Wd[2 * j];
    float p1 = c * Wd[2 * j + 1];
#pragma unroll
    for (int off = 8; off; off >>= 1) {
        p0 += __shfl_xor_sync(0xffffffffu, p0, off, 16);
        p1 += __shfl_xor_sync(0xffffffffu, p1, off, 16);
    }
    if (j == 0) {
        const int elem = e0 + half;
        float l0 = p0 + bd[0];
        float l1 = p1 + bd[1];
        float mx = fmaxf(l0, l1);
        float q0 = ex2f((l0 - mx) * L2E);
        float q1 = ex2f((l1 - mx) * L2E);
        float inv = rcpf(q0 + q1);
        out[2 * elem]     = q0 * inv;
        out[2 * elem + 1] = q1 * inv;
    }
}

extern "C" void kernel_launch(void* const* d_in, const int* in_sizes, int n_in,
                              void* d_out, int out_size)
{
    const float* x  = (const float*)d_in[0];
    const float* Wi = (const float*)d_in[1];
    const float* Wh = (const float*)d_in[2];
    const float* b  = (const float*)d_in[3];
    const float* Wd = (const float*)d_in[4];
    const float* bd = (const float*)d_in[5];
    float* out = (float*)d_out;

    lstm_fused_kernel<<<NB / 8, 128>>>(x, Wi, Wh, b, Wd, bd, out);
}

// round 11
// speedup vs baseline: 1.1208x; 1.0592x over previous
#include <cuda_runtime.h>
#include <cstdint>

// CarryLSTMModel: B=8192, T=1024, D=16, H=16 (4H=64 gates, order i,f,g,o)
// Split-K (R10) + deep prefetch + software-pipelined zx:
//   1 warp = 2 batch elements (A, B).
//   lanes 0-15 hold Wi weights, lanes 16-31 hold Wh weights (same gate cols).
//   Body t computes FFMA(x(t+1), h(t)) in one shared instruction stream;
//   the gate combine uses the SAVED zx(t) from the previous body, so x-work
//   is off the recurrence critical path (ping-pong register sets, unroll-2).
//   x staged through an 8-slot cp.async ring (wait_group 7) -> DRAM latency
//   fully covered. h via double-buffered smem.
// Activations: MUFU.TANH, sig(z)=0.5+0.5*tanh(z/2) (weights pre-scaled).

#define NB 8192
#define NT 1024
#define ND 16
#define NG 64
#define DEPTH 8

typedef unsigned long long u64;
typedef unsigned int u32;

__device__ __forceinline__ u64 pack2(float lo, float hi) {
    u64 r;
    asm("mov.b64 %0, {%1, %2};" : "=l"(r) : "r"(__float_as_uint(lo)), "r"(__float_as_uint(hi)));
    return r;
}
__device__ __forceinline__ void unpack2(u64 v, float& lo, float& hi) {
    u32 a, b;
    asm("mov.b64 {%0, %1}, %2;" : "=r"(a), "=r"(b) : "l"(v));
    lo = __uint_as_float(a);
    hi = __uint_as_float(b);
}
__device__ __forceinline__ u64 ffma2(u64 a, u64 b, u64 c) {
    u64 d;
    asm("fma.rn.f32x2 %0, %1, %2, %3;" : "=l"(d) : "l"(a), "l"(b), "l"(c));
    return d;
}
__device__ __forceinline__ float tanhap(float x) {
    float r; asm("tanh.approx.f32 %0, %1;" : "=f"(r) : "f"(x)); return r;
}
__device__ __forceinline__ float ex2f(float x) {
    float r; asm("ex2.approx.f32 %0, %1;" : "=f"(r) : "f"(x)); return r;
}
__device__ __forceinline__ float rcpf(float x) {
    float r; asm("rcp.approx.f32 %0, %1;" : "=f"(r) : "f"(x)); return r;
}
__device__ __forceinline__ u32 smem_u32(const void* p) {
    return (u32)__cvta_generic_to_shared(p);
}
__device__ __forceinline__ void lds_v2u64(u64& a, u64& b, u32 addr) {
    asm volatile("ld.shared.v2.u64 {%0, %1}, [%2];" : "=l"(a), "=l"(b) : "r"(addr));
}
__device__ __forceinline__ void cp16(u32 dst, const float* src) {
    asm volatile("cp.async.ca.shared.global [%0], [%1], 16;" :: "r"(dst), "l"(src) : "memory");
}
__device__ __forceinline__ void cp_commit() {
    asm volatile("cp.async.commit_group;" ::: "memory");
}
__device__ __forceinline__ void cp_wait7() {
    asm volatile("cp.async.wait_group %0;" :: "n"(DEPTH - 1) : "memory");
}

__global__ __launch_bounds__(128, 4)
void lstm_fused_kernel(const float* __restrict__ x,
                       const float* __restrict__ Wi,
                       const float* __restrict__ Wh,
                       const float* __restrict__ bias,
                       const float* __restrict__ Wd,
                       const float* __restrict__ bd,
                       float* __restrict__ out)
{
    __shared__ float xsm[DEPTH][4][2][16];   // 4 KB: 8-slot x ring
    __shared__ float hsm[2][4][2][16];       // 1 KB: double-buffered h

    const int wib  = threadIdx.x >> 5;
    const int lane = threadIdx.x & 31;
    const int half = lane >> 4;      // 0 = x-group (Wi), 1 = h-group (Wh)
    const int j    = lane & 15;      // gate index / hidden index
    const int e0   = blockIdx.x * 8 + wib * 2;   // warp's element A; B = e0+1

    // sig(z) = 0.5 + 0.5*tanh(z/2): weights/bias pre-scaled so z is the tanh arg.
    const float sI = 0.5f, sF = 0.5f, sG = 1.0f, sO = 0.5f;
    const int ci = j, cf = j + 16, cg = j + 32, co = j + 48;

    const float* Wsrc = (half == 0) ? Wi : Wh;
    u64 wI[8], wF[8], wG[8], wO[8];
#pragma unroll
    for (int m = 0; m < 8; ++m) {
        wI[m] = pack2(Wsrc[(2*m) * NG + ci] * sI, Wsrc[(2*m+1) * NG + ci] * sI);
        wF[m] = pack2(Wsrc[(2*m) * NG + cf] * sF, Wsrc[(2*m+1) * NG + cf] * sF);
        wG[m] = pack2(Wsrc[(2*m) * NG + cg] * sG, Wsrc[(2*m+1) * NG + cg] * sG);
        wO[m] = pack2(Wsrc[(2*m) * NG + co] * sO, Wsrc[(2*m+1) * NG + co] * sO);
    }
    // bias folded once into the x-group accumulator init
    const u64 bI2 = pack2((half == 0) ? bias[ci] * sI : 0.f, 0.f);
    const u64 bF2 = pack2((half == 0) ? bias[cf] * sF : 0.f, 0.f);
    const u64 bG2 = pack2((half == 0) ? bias[cg] * sG : 0.f, 0.f);
    const u64 bO2 = pack2((half == 0) ? bias[co] * sO : 0.f, 0.f);

    // cp.async: lanes 0-7 fetch 8 x 16B = 2 elems x 16 floats per slot
    const float* xsrc = x + (size_t)(e0 + ((lane >> 2) & 1)) * (NT * ND) + (lane & 3) * 4;
    const u32 xdst = smem_u32(&xsm[0][wib][(lane >> 2) & 1][(lane & 3) * 4]);

    const u32 xrd  = smem_u32(&xsm[0][wib][0][0]);   // + slot*512
    const u32 hrd0 = smem_u32(&hsm[0][wib][0][0]);
    const u32 hrd1 = hrd0 + 512;

    float* hw0 = &hsm[0][wib][half][j];
    float* hw1 = hw0 + 128;   // buf stride = 4*2*16 floats

    // init h(0) = 0 in buffer 0; fill the x ring with x(0..7)
    *hw0 = 0.f;
#pragma unroll
    for (int k = 0; k < DEPTH; ++k) {
        if (lane < 8) cp16(xdst + (u32)(k * 512), xsrc + (size_t)k * ND);
        cp_commit();
    }
    cp_wait7();          // x(0) landed
    __syncwarp();

    float c = 0.f;       // cell state: elem A on low lanes, elem B on high lanes

    // FFMA block: loads 2x16 operands at addr, accumulates 4 gates x 2 elems,
    // reduces the packed pairs into zout[0..7] = {IA,FA,GA,OA, IB,FB,GB,OB}.
    auto blockFFMA = [&](u32 addr, float* zout) {
        u64 qA0, qA1, qA2, qA3, qA4, qA5, qA6, qA7;
        u64 qB0, qB1, qB2, qB3, qB4, qB5, qB6, qB7;
        lds_v2u64(qA0, qA1, addr + 0);
        lds_v2u64(qA2, qA3, addr + 16);
        lds_v2u64(qA4, qA5, addr + 32);
        lds_v2u64(qA6, qA7, addr + 48);
        lds_v2u64(qB0, qB1, addr + 64);
        lds_v2u64(qB2, qB3, addr + 80);
        lds_v2u64(qB4, qB5, addr + 96);
        lds_v2u64(qB6, qB7, addr + 112);

        u64 aI = bI2, aF = bF2, aG = bG2, aO = bO2;   // elem A
        u64 eI = bI2, eF = bF2, eG = bG2, eO = bO2;   // elem B
        aI = ffma2(qA0, wI[0], aI); aF = ffma2(qA0, wF[0], aF);
        aG = ffma2(qA0, wG[0], aG); aO = ffma2(qA0, wO[0], aO);
        eI = ffma2(qB0, wI[0], eI); eF = ffma2(qB0, wF[0], eF);
        eG = ffma2(qB0, wG[0], eG); eO = ffma2(qB0, wO[0], eO);
        aI = ffma2(qA1, wI[1], aI); aF = ffma2(qA1, wF[1], aF);
        aG = ffma2(qA1, wG[1], aG); aO = ffma2(qA1, wO[1], aO);
        eI = ffma2(qB1, wI[1], eI); eF = ffma2(qB1, wF[1], eF);
        eG = ffma2(qB1, wG[1], eG); eO = ffma2(qB1, wO[1], eO);
        aI = ffma2(qA2, wI[2], aI); aF = ffma2(qA2, wF[2], aF);
        aG = ffma2(qA2, wG[2], aG); aO = ffma2(qA2, wO[2], aO);
        eI = ffma2(qB2, wI[2], eI); eF = ffma2(qB2, wF[2], eF);
        eG = ffma2(qB2, wG[2], eG); eO = ffma2(qB2, wO[2], eO);
        aI = ffma2(qA3, wI[3], aI); aF = ffma2(qA3, wF[3], aF);
        aG = ffma2(qA3, wG[3], aG); aO = ffma2(qA3, wO[3], aO);
        eI = ffma2(qB3, wI[3], eI); eF = ffma2(qB3, wF[3], eF);
        eG = ffma2(qB3, wG[3], eG); eO = ffma2(qB3, wO[3], eO);
        aI = ffma2(qA4, wI[4], aI); aF = ffma2(qA4, wF[4], aF);
        aG = ffma2(qA4, wG[4], aG); aO = ffma2(qA4, wO[4], aO);
        eI = ffma2(qB4, wI[4], eI); eF = ffma2(qB4, wF[4], eF);
        eG = ffma2(qB4, wG[4], eG); eO = ffma2(qB4, wO[4], eO);
        aI = ffma2(qA5, wI[5], aI); aF = ffma2(qA5, wF[5], aF);
        aG = ffma2(qA5, wG[5], aG); aO = ffma2(qA5, wO[5], aO);
        eI = ffma2(qB5, wI[5], eI); eF = ffma2(qB5, wF[5], eF);
        eG = ffma2(qB5, wG[5], eG); eO = ffma2(qB5, wO[5], eO);
        aI = ffma2(qA6, wI[6], aI); aF = ffma2(qA6, wF[6], aF);
        aG = ffma2(qA6, wG[6], aG); aO = ffma2(qA6, wO[6], aO);
        eI = ffma2(qB6, wI[6], eI); eF = ffma2(qB6, wF[6], eF);
        eG = ffma2(qB6, wG[6], eG); eO = ffma2(qB6, wO[6], eO);
        aI = ffma2(qA7, wI[7], aI); aF = ffma2(qA7, wF[7], aF);
        aG = ffma2(qA7, wG[7], aG); aO = ffma2(qA7, wO[7], aO);
        eI = ffma2(qB7, wI[7], eI); eF = ffma2(qB7, wF[7], eF);
        eG = ffma2(qB7, wG[7], eG); eO = ffma2(qB7, wO[7], eO);

        float lo, hi;
        unpack2(aI, lo, hi); zout[0] = lo + hi;
        unpack2(aF, lo, hi); zout[1] = lo + hi;
        unpack2(aG, lo, hi); zout[2] = lo + hi;
        unpack2(aO, lo, hi); zout[3] = lo + hi;
        unpack2(eI, lo, hi); zout[4] = lo + hi;
        unpack2(eF, lo, hi); zout[5] = lo + hi;
        unpack2(eG, lo, hi); zout[6] = lo + hi;
        unpack2(eO, lo, hi); zout[7] = lo + hi;
    };

    // body for step t: zin = saved zx(t) (x-group), znew receives zx(t+1)|zh(t).
    // hAddr: smem address of h(t); hwPtr: slot for h(t+1).
    auto body = [&](int t, const float* zin, float* znew, u32 hAddr, float* hwPtr) {
        // prefetch x(t+DEPTH) into slot t%8
        int tpre = t + DEPTH;
        if (tpre > NT - 1) tpre = NT - 1;
        if (lane < 8) cp16(xdst + (u32)((t & 7) * 512), xsrc + (size_t)tpre * ND);
        cp_commit();
        cp_wait7();          // x(t+1) landed
        __syncwarp();        // h(t) published by previous body

        const u32 rAddr = half ? hAddr : (xrd + (u32)(((t + 1) & 7) * 512));
        blockFFMA(rAddr, znew);
        // x-group znew = zx(t+1); h-group znew = zh(t)

        // combine: low lanes finalize elem A's z(t), high lanes elem B's.
        float zI, zF, zG, zO;
        {
            float sI_ = half ? znew[0] : zin[4];
            float sF_ = half ? znew[1] : zin[5];
            float sG_ = half ? znew[2] : zin[6];
            float sO_ = half ? znew[3] : zin[7];
            float rI = __shfl_xor_sync(0xffffffffu, sI_, 16);
            float rF = __shfl_xor_sync(0xffffffffu, sF_, 16);
            float rG = __shfl_xor_sync(0xffffffffu, sG_, 16);
            float rO = __shfl_xor_sync(0xffffffffu, sO_, 16);
            zI = (half ? znew[4] : zin[0]) + rI;
            zF = (half ? znew[5] : zin[1]) + rF;
            zG = (half ? znew[6] : zin[2]) + rG;
            zO = (half ? znew[7] : zin[3]) + rO;
        }

        float vI = fmaf(0.5f, tanhap(zI), 0.5f);   // sig
        float vF = fmaf(0.5f, tanhap(zF), 0.5f);   // sig
        float vG = tanhap(zG);                     // tanh
        float vO = fmaf(0.5f, tanhap(zO), 0.5f);   // sig
        c = fmaf(vF, c, vI * vG);
        float hv = vO * tanhap(c);

        *hwPtr = hv;   // h(t+1)
    };

    // prologue: compute zx(0) (x-group) with h(0)=0 partials on h-group (discarded)
    float zA[8], zB[8];
    blockFFMA(half ? hrd0 : xrd, zA);

#pragma unroll 1
    for (int t = 0; t < NT; t += 2) {
        body(t,     zA, zB, hrd0, hw1);   // even: h in buf0, writes buf1
        body(t + 1, zB, zA, hrd1, hw0);   // odd:  h in buf1, writes buf0
    }

    // head: logits = c_T @ Wd + bd, softmax over 2 classes.
    const float L2E = 1.44269504088896340736f;
    float p0 = c * Wd[2 * j];
    float p1 = c * Wd[2 * j + 1];
#pragma unroll
    for (int off = 8; off; off >>= 1) {
        p0 += __shfl_xor_sync(0xffffffffu, p0, off, 16);
        p1 += __shfl_xor_sync(0xffffffffu, p1, off, 16);
    }
    if (j == 0) {
        const int elem = e0 + half;
        float l0 = p0 + bd[0];
        float l1 = p1 + bd[1];
        float mx = fmaxf(l0, l1);
        float q0 = ex2f((l0 - mx) * L2E);
        float q1 = ex2f((l1 - mx) * L2E);
        float inv = rcpf(q0 + q1);
        out[2 * elem]     = q0 * inv;
        out[2 * elem + 1] = q1 * inv;
    }
}

extern "C" void kernel_launch(void* const* d_in, const int* in_sizes, int n_in,
                              void* d_out, int out_size)
{
    const float* x  = (const float*)d_in[0];
    const float* Wi = (const float*)d_in[1];
    const float* Wh = (const float*)d_in[2];
    const float* b  = (const float*)d_in[3];
    const float* Wd = (const float*)d_in[4];
    const float* bd = (const float*)d_in[5];
    float* out = (float*)d_out;

    lstm_fused_kernel<<<NB / 8, 128>>>(x, Wi, Wh, b, Wd, bd, out);
}

// round 12
// speedup vs baseline: 1.2061x; 1.0761x over previous
#include <cuda_runtime.h>
#include <cstdint>

// CarryLSTMModel: B=8192, T=1024, D=16, H=16 (4H=64 gates, order i,f,g,o)
// Split-K + software-pipelined zx (R11 dataflow) with full compile-time
// addressing:
//   1 warp = 2 batch elements (A, B); lanes 0-15 hold Wi, lanes 16-31 hold Wh.
//   Body t computes FFMA(x(t+1) | h(t)) in one shared instruction stream;
//   the gate combine uses the SAVED zx(t) from the previous body.
//   x: 8-slot cp.async ring, 2 steps fetched per LDGSTS (lanes<16), wait_group 3.
//   h: 8-slot smem ring storing h(t) in slot (t+1)&7 -> read address formula
//      identical to x's (rbase + ((s+1)&7)*512, rbase hoisted per lane).
//   Time loop unrolled x8 -> all ring indices are immediates; clamp-free
//   epilogue (last 8 steps run after one full cp.async drain, no cp ops).
// Activations: MUFU.TANH, sig(z)=0.5+0.5*tanh(z/2) (weights pre-scaled).

#define NB 8192
#define NT 1024
#define ND 16
#define NG 64

typedef unsigned long long u64;
typedef unsigned int u32;

__device__ __forceinline__ u64 pack2(float lo, float hi) {
    u64 r;
    asm("mov.b64 %0, {%1, %2};" : "=l"(r) : "r"(__float_as_uint(lo)), "r"(__float_as_uint(hi)));
    return r;
}
__device__ __forceinline__ void unpack2(u64 v, float& lo, float& hi) {
    u32 a, b;
    asm("mov.b64 {%0, %1}, %2;" : "=r"(a), "=r"(b) : "l"(v));
    lo = __uint_as_float(a);
    hi = __uint_as_float(b);
}
__device__ __forceinline__ u64 ffma2(u64 a, u64 b, u64 c) {
    u64 d;
    asm("fma.rn.f32x2 %0, %1, %2, %3;" : "=l"(d) : "l"(a), "l"(b), "l"(c));
    return d;
}
__device__ __forceinline__ float tanhap(float x) {
    float r; asm("tanh.approx.f32 %0, %1;" : "=f"(r) : "f"(x)); return r;
}
__device__ __forceinline__ float ex2f(float x) {
    float r; asm("ex2.approx.f32 %0, %1;" : "=f"(r) : "f"(x)); return r;
}
__device__ __forceinline__ float rcpf(float x) {
    float r; asm("rcp.approx.f32 %0, %1;" : "=f"(r) : "f"(x)); return r;
}
__device__ __forceinline__ u32 smem_u32(const void* p) {
    return (u32)__cvta_generic_to_shared(p);
}
__device__ __forceinline__ void lds_v2u64(u64& a, u64& b, u32 addr) {
    asm volatile("ld.shared.v2.u64 {%0, %1}, [%2];" : "=l"(a), "=l"(b) : "r"(addr));
}
__device__ __forceinline__ void sts32(u32 addr, float v) {
    asm volatile("st.shared.f32 [%0], %1;" :: "r"(addr), "f"(v) : "memory");
}
__device__ __forceinline__ void cp16(u32 dst, const float* src) {
    asm volatile("cp.async.ca.shared.global [%0], [%1], 16;" :: "r"(dst), "l"(src) : "memory");
}
__device__ __forceinline__ void cp_commit() {
    asm volatile("cp.async.commit_group;" ::: "memory");
}
__device__ __forceinline__ void cp_wait3() {
    asm volatile("cp.async.wait_group 3;" ::: "memory");
}
__device__ __forceinline__ void cp_wait0() {
    asm volatile("cp.async.wait_group 0;" ::: "memory");
}

__global__ __launch_bounds__(128, 4)
void lstm_fused_kernel(const float* __restrict__ x,
                       const float* __restrict__ Wi,
                       const float* __restrict__ Wh,
                       const float* __restrict__ bias,
                       const float* __restrict__ Wd,
                       const float* __restrict__ bd,
                       float* __restrict__ out)
{
    __shared__ __align__(16) float xsm[8][4][2][16];   // 4 KB x ring
    __shared__ __align__(16) float hsm[8][4][2][16];   // 4 KB h ring

    const int wib  = threadIdx.x >> 5;
    const int lane = threadIdx.x & 31;
    const int half = lane >> 4;      // 0 = x-group (Wi), 1 = h-group (Wh)
    const int j    = lane & 15;      // gate index / hidden index
    const int e0   = blockIdx.x * 8 + wib * 2;   // warp's element A; B = e0+1

    const float sI = 0.5f, sF = 0.5f, sG = 1.0f, sO = 0.5f;
    const int ci = j, cf = j + 16, cg = j + 32, co = j + 48;

    const float* Wsrc = (half == 0) ? Wi : Wh;
    u64 wI[8], wF[8], wG[8], wO[8];
#pragma unroll
    for (int m = 0; m < 8; ++m) {
        wI[m] = pack2(Wsrc[(2*m) * NG + ci] * sI, Wsrc[(2*m+1) * NG + ci] * sI);
        wF[m] = pack2(Wsrc[(2*m) * NG + cf] * sF, Wsrc[(2*m+1) * NG + cf] * sF);
        wG[m] = pack2(Wsrc[(2*m) * NG + cg] * sG, Wsrc[(2*m+1) * NG + cg] * sG);
        wO[m] = pack2(Wsrc[(2*m) * NG + co] * sO, Wsrc[(2*m+1) * NG + co] * sO);
    }
    const u64 bI2 = pack2((half == 0) ? bias[ci] * sI : 0.f, 0.f);
    const u64 bF2 = pack2((half == 0) ? bias[cf] * sF : 0.f, 0.f);
    const u64 bG2 = pack2((half == 0) ? bias[cg] * sG : 0.f, 0.f);
    const u64 bO2 = pack2((half == 0) ? bias[co] * sO : 0.f, 0.f);

    // paired prefetch (lanes<16): slot parity = lane>>3, elem = (lane>>2)&1
    const float* xpref = x + (size_t)(e0 + ((lane >> 2) & 1)) * (NT * ND)
                           + (lane & 3) * 4 + (size_t)((lane >> 3) & 1) * ND;
    const u32 xdst2 = smem_u32(&xsm[(lane >> 3) & 1][wib][(lane >> 2) & 1][(lane & 3) * 4]);

    const u32 xrd = smem_u32(&xsm[0][wib][0][0]);
    const u32 hrd = smem_u32(&hsm[0][wib][0][0]);
    const u32 rbase  = half ? hrd : xrd;          // per-lane operand base
    const u32 hwaddr = smem_u32(&hsm[0][wib][half][j]);   // + slot*512

    // h(0) lives in slot 1 (slot formula: h(t) in slot (t+1)&7)
    sts32(hwaddr + 512, 0.f);

    // prologue prefetch x(0..7) as 4 paired groups
#pragma unroll
    for (int k2 = 0; k2 < 8; k2 += 2) {
        if (lane < 16) cp16(xdst2 + (u32)(k2 * 512), xpref + k2 * ND);
        cp_commit();
    }
    cp_wait3();          // x(0),x(1) landed
    __syncwarp();

    float c = 0.f;
    float zbuf0[8], zbuf1[8];

    // FFMA block: loads 2x16 operands at addr, accumulates 4 gates x 2 elems,
    // reduces packed pairs into zout[0..7] = {IA,FA,GA,OA, IB,FB,GB,OB}.
    auto blockFFMA = [&](u32 addr, float* zout) {
        u64 qA0, qA1, qA2, qA3, qA4, qA5, qA6, qA7;
        u64 qB0, qB1, qB2, qB3, qB4, qB5, qB6, qB7;
        lds_v2u64(qA0, qA1, addr + 0);
        lds_v2u64(qA2, qA3, addr + 16);
        lds_v2u64(qA4, qA5, addr + 32);
        lds_v2u64(qA6, qA7, addr + 48);
        lds_v2u64(qB0, qB1, addr + 64);
        lds_v2u64(qB2, qB3, addr + 80);
        lds_v2u64(qB4, qB5, addr + 96);
        lds_v2u64(qB6, qB7, addr + 112);

        u64 aI = bI2, aF = bF2, aG = bG2, aO = bO2;   // elem A
        u64 eI = bI2, eF = bF2, eG = bG2, eO = bO2;   // elem B
        aI = ffma2(qA0, wI[0], aI); aF = ffma2(qA0, wF[0], aF);
        aG = ffma2(qA0, wG[0], aG); aO = ffma2(qA0, wO[0], aO);
        eI = ffma2(qB0, wI[0], eI); eF = ffma2(qB0, wF[0], eF);
        eG = ffma2(qB0, wG[0], eG); eO = ffma2(qB0, wO[0], eO);
        aI = ffma2(qA1, wI[1], aI); aF = ffma2(qA1, wF[1], aF);
        aG = ffma2(qA1, wG[1], aG); aO = ffma2(qA1, wO[1], aO);
        eI = ffma2(qB1, wI[1], eI); eF = ffma2(qB1, wF[1], eF);
        eG = ffma2(qB1, wG[1], eG); eO = ffma2(qB1, wO[1], eO);
        aI = ffma2(qA2, wI[2], aI); aF = ffma2(qA2, wF[2], aF);
        aG = ffma2(qA2, wG[2], aG); aO = ffma2(qA2, wO[2], aO);
        eI = ffma2(qB2, wI[2], eI); eF = ffma2(qB2, wF[2], eF);
        eG = ffma2(qB2, wG[2], eG); eO = ffma2(qB2, wO[2], eO);
        aI = ffma2(qA3, wI[3], aI); aF = ffma2(qA3, wF[3], aF);
        aG = ffma2(qA3, wG[3], aG); aO = ffma2(qA3, wO[3], aO);
        eI = ffma2(qB3, wI[3], eI); eF = ffma2(qB3, wF[3], eF);
        eG = ffma2(qB3, wG[3], eG); eO = ffma2(qB3, wO[3], eO);
        aI = ffma2(qA4, wI[4], aI); aF = ffma2(qA4, wF[4], aF);
        aG = ffma2(qA4, wG[4], aG); aO = ffma2(qA4, wO[4], aO);
        eI = ffma2(qB4, wI[4], eI); eF = ffma2(qB4, wF[4], eF);
        eG = ffma2(qB4, wG[4], eG); eO = ffma2(qB4, wO[4], eO);
        aI = ffma2(qA5, wI[5], aI); aF = ffma2(qA5, wF[5], aF);
        aG = ffma2(qA5, wG[5], aG); aO = ffma2(qA5, wO[5], aO);
        eI = ffma2(qB5, wI[5], eI); eF = ffma2(qB5, wF[5], eF);
        eG = ffma2(qB5, wG[5], eG); eO = ffma2(qB5, wO[5], eO);
        aI = ffma2(qA6, wI[6], aI); aF = ffma2(qA6, wF[6], aF);
        aG = ffma2(qA6, wG[6], aG); aO = ffma2(qA6, wO[6], aO);
        eI = ffma2(qB6, wI[6], eI); eF = ffma2(qB6, wF[6], eF);
        eG = ffma2(qB6, wG[6], eG); eO = ffma2(qB6, wO[6], eO);
        aI = ffma2(qA7, wI[7], aI); aF = ffma2(qA7, wF[7], aF);
        aG = ffma2(qA7, wG[7], aG); aO = ffma2(qA7, wO[7], aO);
        eI = ffma2(qB7, wI[7], eI); eF = ffma2(qB7, wF[7], eF);
        eG = ffma2(qB7, wG[7], eG); eO = ffma2(qB7, wO[7], eO);

        float lo, hi;
        unpack2(aI, lo, hi); zout[0] = lo + hi;
        unpack2(aF, lo, hi); zout[1] = lo + hi;
        unpack2(aG, lo, hi); zout[2] = lo + hi;
        unpack2(aO, lo, hi); zout[3] = lo + hi;
        unpack2(eI, lo, hi); zout[4] = lo + hi;
        unpack2(eF, lo, hi); zout[5] = lo + hi;
        unpack2(eG, lo, hi); zout[6] = lo + hi;
        unpack2(eO, lo, hi); zout[7] = lo + hi;
    };

    // one time step; s = t & 7 (compile-time under unroll)
    auto body = [&](int s, const float* zin, float* znew, const float* xpf, bool pf) {
        if (pf) {
            if ((s & 1) == 0) {
                if (lane < 16) cp16(xdst2 + (u32)(s * 512), xpf + s * ND);
                cp_commit();
            }
            cp_wait3();
        }
        __syncwarp();   // orders prev-step h STS before this step's LDS

        blockFFMA(rbase + (u32)(((s + 1) & 7) * 512), znew);
        // x-group znew = zx(t+1); h-group znew = zh(t)

        float zI, zF, zG, zO;
        {
            float sI_ = half ? znew[0] : zin[4];
            float sF_ = half ? znew[1] : zin[5];
            float sG_ = half ? znew[2] : zin[6];
            float sO_ = half ? znew[3] : zin[7];
            float rI = __shfl_xor_sync(0xffffffffu, sI_, 16);
            float rF = __shfl_xor_sync(0xffffffffu, sF_, 16);
            float rG = __shfl_xor_sync(0xffffffffu, sG_, 16);
            float rO = __shfl_xor_sync(0xffffffffu, sO_, 16);
            zI = (half ? znew[4] : zin[0]) + rI;
            zF = (half ? znew[5] : zin[1]) + rF;
            zG = (half ? znew[6] : zin[2]) + rG;
            zO = (half ? znew[7] : zin[3]) + rO;
        }

        float vI = fmaf(0.5f, tanhap(zI), 0.5f);   // sig
        float vF = fmaf(0.5f, tanhap(zF), 0.5f);   // sig
        float vG = tanhap(zG);                     // tanh
        float vO = fmaf(0.5f, tanhap(zO), 0.5f);   // sig
        c = fmaf(vF, c, vI * vG);
        float hv = vO * tanhap(c);

        // h(t+1) -> slot (t+2)&7
        sts32(hwaddr + (u32)(((s + 2) & 7) * 512), hv);
    };

    // prologue: zx(0) on x-group (h-group reads h(0)=0 from slot 1; unused)
    blockFFMA(rbase + (u32)(half * 512), zbuf0);

    const float* xpf = xpref + 8 * ND;   // main-loop prefetch source base

#pragma unroll 1
    for (int tb = 0; tb < NT - 8; tb += 8) {
#pragma unroll
        for (int s = 0; s < 8; ++s) {
            if ((s & 1) == 0) body(s, zbuf0, zbuf1, xpf, true);
            else              body(s, zbuf1, zbuf0, xpf, true);
        }
        xpf += 8 * ND;
    }

    // epilogue: last 8 steps, all x already resident
    cp_wait0();
#pragma unroll
    for (int s = 0; s < 8; ++s) {
        if ((s & 1) == 0) body(s, zbuf0, zbuf1, (const float*)0, false);
        else              body(s, zbuf1, zbuf0, (const float*)0, false);
    }

    // head: logits = c_T @ Wd + bd, softmax over 2 classes.
    const float L2E = 1.44269504088896340736f;
    float p0 = c * Wd[2 * j];
    float p1 = c * Wd[2 * j + 1];
#pragma unroll
    for (int off = 8; off; off >>= 1) {
        p0 += __shfl_xor_sync(0xffffffffu, p0, off, 16);
        p1 += __shfl_xor_sync(0xffffffffu, p1, off, 16);
    }
    if (j == 0) {
        const int elem = e0 + half;
        float l0 = p0 + bd[0];
        float l1 = p1 + bd[1];
        float mx = fmaxf(l0, l1);
        float q0 = ex2f((l0 - mx) * L2E);
        float q1 = ex2f((l1 - mx) * L2E);
        float inv = rcpf(q0 + q1);
        out[2 * elem]     = q0 * inv;
        out[2 * elem + 1] = q1 * inv;
    }
}

extern "C" void kernel_launch(void* const* d_in, const int* in_sizes, int n_in,
                              void* d_out, int out_size)
{
    const float* x  = (const float*)d_in[0];
    const float* Wi = (const float*)d_in[1];
    const float* Wh = (const float*)d_in[2];
    const float* b  = (const float*)d_in[3];
    const float* Wd = (const float*)d_in[4];
    const float* bd = (const float*)d_in[5];
    float* out = (float*)d_out;

    lstm_fused_kernel<<<NB / 8, 128>>>(x, Wi, Wh, b, Wd, bd, out);
}

// round 13
// speedup vs baseline: 1.2417x; 1.0296x over previous
#include <cuda_runtime.h>
#include <cstdint>

// CarryLSTMModel: B=8192, T=1024, D=16, H=16 (4H=64 gates, order i,f,g,o)
// Split-K, de-pipelined (combine-fresh) + kept/sent addressing:
//   1 warp = 2 batch elements (A, B); lanes 0-15 hold Wi, lanes 16-31 hold Wh.
//   Body t: FFMA(x(t) | h(t)) in one shared stream. Kept/sent operand bases:
//   each lane accumulates its FINALIZED element (x-lanes: A, h-lanes: B) into
//   chains 0-3 and the sent element into chains 4-7, so the combine is
//   uniformly z = zk[g] + shfl_xor(zs[g], 16) — no selects, no saved arrays.
//   Bias folded into the first FFMA2 of each chain (x-lanes carry bias).
//   x: 16-slot cp.async ring, paired fetch (2 steps / commit, lanes<16),
//      wait_group 3 -> fetch distance 8-9, no slot conflicts, margin 2.
//   h: 8-slot smem ring, h(t) in slot t&7. Time loop unrolled x8.
// Activations: MUFU.TANH, sig(z)=0.5+0.5*tanh(z/2) (weights pre-scaled).

#define NB 8192
#define NT 1024
#define ND 16
#define NG 64

typedef unsigned long long u64;
typedef unsigned int u32;

__device__ __forceinline__ u64 pack2(float lo, float hi) {
    u64 r;
    asm("mov.b64 %0, {%1, %2};" : "=l"(r) : "r"(__float_as_uint(lo)), "r"(__float_as_uint(hi)));
    return r;
}
__device__ __forceinline__ void unpack2(u64 v, float& lo, float& hi) {
    u32 a, b;
    asm("mov.b64 {%0, %1}, %2;" : "=r"(a), "=r"(b) : "l"(v));
    lo = __uint_as_float(a);
    hi = __uint_as_float(b);
}
__device__ __forceinline__ u64 ffma2(u64 a, u64 b, u64 c) {
    u64 d;
    asm("fma.rn.f32x2 %0, %1, %2, %3;" : "=l"(d) : "l"(a), "l"(b), "l"(c));
    return d;
}
__device__ __forceinline__ float tanhap(float x) {
    float r; asm("tanh.approx.f32 %0, %1;" : "=f"(r) : "f"(x)); return r;
}
__device__ __forceinline__ float ex2f(float x) {
    float r; asm("ex2.approx.f32 %0, %1;" : "=f"(r) : "f"(x)); return r;
}
__device__ __forceinline__ float rcpf(float x) {
    float r; asm("rcp.approx.f32 %0, %1;" : "=f"(r) : "f"(x)); return r;
}
__device__ __forceinline__ u32 smem_u32(const void* p) {
    return (u32)__cvta_generic_to_shared(p);
}
__device__ __forceinline__ void lds_v2u64(u64& a, u64& b, u32 addr) {
    asm volatile("ld.shared.v2.u64 {%0, %1}, [%2];" : "=l"(a), "=l"(b) : "r"(addr));
}
__device__ __forceinline__ void sts32(u32 addr, float v) {
    asm volatile("st.shared.f32 [%0], %1;" :: "r"(addr), "f"(v) : "memory");
}
__device__ __forceinline__ void cp16(u32 dst, const float* src) {
    asm volatile("cp.async.ca.shared.global [%0], [%1], 16;" :: "r"(dst), "l"(src) : "memory");
}
__device__ __forceinline__ void cp_commit() {
    asm volatile("cp.async.commit_group;" ::: "memory");
}
__device__ __forceinline__ void cp_wait3() {
    asm volatile("cp.async.wait_group 3;" ::: "memory");
}
__device__ __forceinline__ void cp_wait0() {
    asm volatile("cp.async.wait_group 0;" ::: "memory");
}

__global__ __launch_bounds__(128, 4)
void lstm_fused_kernel(const float* __restrict__ x,
                       const float* __restrict__ Wi,
                       const float* __restrict__ Wh,
                       const float* __restrict__ bias,
                       const float* __restrict__ Wd,
                       const float* __restrict__ bd,
                       float* __restrict__ out)
{
    __shared__ __align__(16) float xsm[16][4][2][16];   // 8 KB: 16-slot x ring
    __shared__ __align__(16) float hsm[8][4][2][16];    // 4 KB: 8-slot h ring

    const int wib  = threadIdx.x >> 5;
    const int lane = threadIdx.x & 31;
    const int half = lane >> 4;      // 0 = x-group (Wi), 1 = h-group (Wh)
    const int j    = lane & 15;      // gate index / hidden index
    const int e0   = blockIdx.x * 8 + wib * 2;   // warp's element A; B = e0+1

    const float sI = 0.5f, sF = 0.5f, sG = 1.0f, sO = 0.5f;
    const int ci = j, cf = j + 16, cg = j + 32, co = j + 48;

    const float* Wsrc = (half == 0) ? Wi : Wh;
    u64 wI[8], wF[8], wG[8], wO[8];
#pragma unroll
    for (int m = 0; m < 8; ++m) {
        wI[m] = pack2(Wsrc[(2*m) * NG + ci] * sI, Wsrc[(2*m+1) * NG + ci] * sI);
        wF[m] = pack2(Wsrc[(2*m) * NG + cf] * sF, Wsrc[(2*m+1) * NG + cf] * sF);
        wG[m] = pack2(Wsrc[(2*m) * NG + cg] * sG, Wsrc[(2*m+1) * NG + cg] * sG);
        wO[m] = pack2(Wsrc[(2*m) * NG + co] * sO, Wsrc[(2*m+1) * NG + co] * sO);
    }
    // bias carried by x-lanes only (added exactly once per element)
    const u64 bI2 = pack2((half == 0) ? bias[ci] * sI : 0.f, 0.f);
    const u64 bF2 = pack2((half == 0) ? bias[cf] * sF : 0.f, 0.f);
    const u64 bG2 = pack2((half == 0) ? bias[cg] * sG : 0.f, 0.f);
    const u64 bO2 = pack2((half == 0) ? bias[co] * sO : 0.f, 0.f);

    // paired prefetch (lanes<16): pair-slot = (lane>>3)&1, elem = (lane>>2)&1
    const float* xpref = x + (size_t)(e0 + ((lane >> 2) & 1)) * (NT * ND)
                           + (lane & 3) * 4 + (size_t)((lane >> 3) & 1) * ND;
    const u32 xdst2 = smem_u32(&xsm[(lane >> 3) & 1][wib][(lane >> 2) & 1][(lane & 3) * 4]);

    const u32 xrd = smem_u32(&xsm[0][wib][0][0]);
    const u32 hrd = smem_u32(&hsm[0][wib][0][0]);
    // kept/sent bases: x-lanes kept=A(+0), sent=B(+64); h-lanes kept=B(+64), sent=A(+0)
    const u32 hKept = hrd + 64, hSent = hrd;
    const u32 hwaddr = smem_u32(&hsm[0][wib][half][j]);   // + slot*512

    // h(0) = 0 in slot 0
    sts32(hwaddr, 0.f);

    // prologue: fetch x(0..7) as 4 paired groups into slots 0..7
#pragma unroll
    for (int k2 = 0; k2 < 8; k2 += 2) {
        if (lane < 16) cp16(xdst2 + (u32)(k2 * 512), xpref + k2 * ND);
        cp_commit();
    }
    cp_wait3();          // x(0..1) landed
    __syncwarp();

    float c = 0.f;

    // one time step; s = t & 7 (compile-time under unroll).
    // kb/sb: kept/sent operand bases for this 8-block (x side includes ring toggle).
    auto body = [&](int s, u32 kb, u32 sb, u32 xdstB, const float* xpf, bool pf) {
        if (pf) {
            if ((s & 1) == 0) {
                if (lane < 16) cp16(xdstB + (u32)(s * 512), xpf + s * ND);
                cp_commit();
                cp_wait3();
            }
        }
        __syncwarp();   // orders prev-step h STS before this step's LDS

        const u32 ka = kb + (u32)(s * 512);
        const u32 sa = sb + (u32)(s * 512);
        u64 k0, k1, k2, k3, k4, k5, k6, k7;
        u64 s0, s1, s2, s3, s4, s5, s6, s7;
        lds_v2u64(k0, k1, ka + 0);
        lds_v2u64(k2, k3, ka + 16);
        lds_v2u64(k4, k5, ka + 32);
        lds_v2u64(k6, k7, ka + 48);
        lds_v2u64(s0, s1, sa + 0);
        lds_v2u64(s2, s3, sa + 16);
        lds_v2u64(s4, s5, sa + 32);
        lds_v2u64(s6, s7, sa + 48);

        // kept chains (bias-folded init) and sent chains
        u64 aI = ffma2(k0, wI[0], bI2), aF = ffma2(k0, wF[0], bF2);
        u64 aG = ffma2(k0, wG[0], bG2), aO = ffma2(k0, wO[0], bO2);
        u64 eI = ffma2(s0, wI[0], bI2), eF = ffma2(s0, wF[0], bF2);
        u64 eG = ffma2(s0, wG[0], bG2), eO = ffma2(s0, wO[0], bO2);
        aI = ffma2(k1, wI[1], aI); aF = ffma2(k1, wF[1], aF);
        aG = ffma2(k1, wG[1], aG); aO = ffma2(k1, wO[1], aO);
        eI = ffma2(s1, wI[1], eI); eF = ffma2(s1, wF[1], eF);
        eG = ffma2(s1, wG[1], eG); eO = ffma2(s1, wO[1], eO);
        aI = ffma2(k2, wI[2], aI); aF = ffma2(k2, wF[2], aF);
        aG = ffma2(k2, wG[2], aG); aO = ffma2(k2, wO[2], aO);
        eI = ffma2(s2, wI[2], eI); eF = ffma2(s2, wF[2], eF);
        eG = ffma2(s2, wG[2], eG); eO = ffma2(s2, wO[2], eO);
        aI = ffma2(k3, wI[3], aI); aF = ffma2(k3, wF[3], aF);
        aG = ffma2(k3, wG[3], aG); aO = ffma2(k3, wO[3], aO);
        eI = ffma2(s3, wI[3], eI); eF = ffma2(s3, wF[3], eF);
        eG = ffma2(s3, wG[3], eG); eO = ffma2(s3, wO[3], eO);
        aI = ffma2(k4, wI[4], aI); aF = ffma2(k4, wF[4], aF);
        aG = ffma2(k4, wG[4], aG); aO = ffma2(k4, wO[4], aO);
        eI = ffma2(s4, wI[4], eI); eF = ffma2(s4, wF[4], eF);
        eG = ffma2(s4, wG[4], eG); eO = ffma2(s4, wO[4], eO);
        aI = ffma2(k5, wI[5], aI); aF = ffma2(k5, wF[5], aF);
        aG = ffma2(k5, wG[5], aG); aO = ffma2(k5, wO[5], aO);
        eI = ffma2(s5, wI[5], eI); eF = ffma2(s5, wF[5], eF);
        eG = ffma2(s5, wG[5], eG); eO = ffma2(s5, wO[5], eO);
        aI = ffma2(k6, wI[6], aI); aF = ffma2(k6, wF[6], aF);
        aG = ffma2(k6, wG[6], aG); aO = ffma2(k6, wO[6], aO);
        eI = ffma2(s6, wI[6], eI); eF = ffma2(s6, wF[6], eF);
        eG = ffma2(s6, wG[6], eG); eO = ffma2(s6, wO[6], eO);
        aI = ffma2(k7, wI[7], aI); aF = ffma2(k7, wF[7], aF);
        aG = ffma2(k7, wG[7], aG); aO = ffma2(k7, wO[7], aO);
        eI = ffma2(s7, wI[7], eI); eF = ffma2(s7, wF[7], eF);
        eG = ffma2(s7, wG[7], eG); eO = ffma2(s7, wO[7], eO);

        float lo, hi;
        float zkI, zkF, zkG, zkO, zsI, zsF, zsG, zsO;
        unpack2(aI, lo, hi); zkI = lo + hi;
        unpack2(aF, lo, hi); zkF = lo + hi;
        unpack2(aG, lo, hi); zkG = lo + hi;
        unpack2(aO, lo, hi); zkO = lo + hi;
        unpack2(eI, lo, hi); zsI = lo + hi;
        unpack2(eF, lo, hi); zsF = lo + hi;
        unpack2(eG, lo, hi); zsG = lo + hi;
        unpack2(eO, lo, hi); zsO = lo + hi;

        // uniform combine: kept + partner's sent
        float zI = zkI + __shfl_xor_sync(0xffffffffu, zsI, 16);
        float zF = zkF + __shfl_xor_sync(0xffffffffu, zsF, 16);
        float zG = zkG + __shfl_xor_sync(0xffffffffu, zsG, 16);
        float zO = zkO + __shfl_xor_sync(0xffffffffu, zsO, 16);

        float vI = fmaf(0.5f, tanhap(zI), 0.5f);   // sig
        float vF = fmaf(0.5f, tanhap(zF), 0.5f);   // sig
        float vG = tanhap(zG);                     // tanh
        float vO = fmaf(0.5f, tanhap(zO), 0.5f);   // sig
        c = fmaf(vF, c, vI * vG);
        float hv = vO * tanhap(c);

        // h(t+1) -> slot (t+1)&7
        sts32(hwaddr + (u32)((((s + 1) & 7)) * 512), hv);
    };

    const float* xpf = xpref + 8 * ND;   // fetch base for block 0 (x(tb+8+s))

#pragma unroll 1
    for (int tb = 0; tb < NT - 8; tb += 8) {
        const u32 tog   = (u32)(tb & 8) * 512;         // x ring half for reads
        const u32 kb    = half ? hKept : (xrd + tog);
        const u32 sb    = half ? hSent : (xrd + 64 + tog);
        const u32 xdstB = xdst2 + (tog ^ 4096);        // fetch into other half
#pragma unroll
        for (int s = 0; s < 8; ++s)
            body(s, kb, sb, xdstB, xpf, true);
        xpf += 8 * ND;
    }

    // final block (tb = NT-8): all x already fetched; drain and run fetch-free
    cp_wait0();
    {
        const u32 tog = (u32)((NT - 8) & 8) * 512;
        const u32 kb  = half ? hKept : (xrd + tog);
        const u32 sb  = half ? hSent : (xrd + 64 + tog);
#pragma unroll
        for (int s = 0; s < 8; ++s)
            body(s, kb, sb, 0u, (const float*)0, false);
    }

    // head: logits = c_T @ Wd + bd, softmax over 2 classes.
    // x-lanes hold elem A's c, h-lanes elem B's — reduce within each half.
    const float L2E = 1.44269504088896340736f;
    float p0 = c * Wd[2 * j];
    float p1 = c * Wd[2 * j + 1];
#pragma unroll
    for (int off = 8; off; off >>= 1) {
        p0 += __shfl_xor_sync(0xffffffffu, p0, off, 16);
        p1 += __shfl_xor_sync(0xffffffffu, p1, off, 16);
    }
    if (j == 0) {
        const int elem = e0 + half;
        float l0 = p0 + bd[0];
        float l1 = p1 + bd[1];
        float mx = fmaxf(l0, l1);
        float q0 = ex2f((l0 - mx) * L2E);
        float q1 = ex2f((l1 - mx) * L2E);
        float inv = rcpf(q0 + q1);
        out[2 * elem]     = q0 * inv;
        out[2 * elem + 1] = q1 * inv;
    }
}

extern "C" void kernel_launch(void* const* d_in, const int* in_sizes, int n_in,
                              void* d_out, int out_size)
{
    const float* x  = (const float*)d_in[0];
    const float* Wi = (const float*)d_in[1];
    const float* Wh = (const float*)d_in[2];
    const float* b  = (const float*)d_in[3];
    const float* Wd = (const float*)d_in[4];
    const float* bd = (const float*)d_in[5];
    float* out = (float*)d_out;

    lstm_fused_kernel<<<NB / 8, 128>>>(x, Wi, Wh, b, Wd, bd, out);
}

// round 14
// speedup vs baseline: 1.9222x; 1.5480x over previous
#include <cuda_runtime.h>
#include <cstdint>

// CarryLSTMModel: B=8192, T=1024, D=16, H=16 (4H=64 gates, order i,f,g,o)
// Tensor-core rewrite: tf32 mma.sync.m16n8k8.
//   1 warp = 16 batch elements, all 1024 steps.
//   Per step: z[16x64] = x[16x16]@Wi + h[16x16]@Wh + b via 32 HMMA
//   (8 gate-groups x {x-k0, x-k1, h-k0, h-k1}); bias enters as the C operand
//   of the first mma (free). Weights pre-scaled (0.5 for i/f/o, 1 for g) so
//   z is directly the tanh argument: sig(z)=0.5+0.5*tanh(z/2), MUFU.TANH.
//   All 4 gates of (elem e, hidden j) live on ONE lane across C-frags
//   {j/8, +2, +4, +6} -> lane-local activations, c-state in registers (8/lane).
//   h relayout C->A via smem (stride-20 rows: conflict-free A-frag LDS),
//   double-buffered. x via 4-slot cp.async ring (distance 2, wait_group 1).
//   Block 128 = 4 warps (one per SMSP via wid%4), grid 128.

#define NB 8192
#define NT 1024
#define ND 16
#define NG 64
#define RS 20                  // padded row stride (floats)
#define SLOT_B (16 * RS * 4)   // 1280 bytes per 16x16 tile

typedef unsigned int u32;

__device__ __forceinline__ u32 smem_u32(const void* p) {
    return (u32)__cvta_generic_to_shared(p);
}
__device__ __forceinline__ float tanhap(float x) {
    float r; asm("tanh.approx.f32 %0, %1;" : "=f"(r) : "f"(x)); return r;
}
__device__ __forceinline__ float ex2f(float x) {
    float r; asm("ex2.approx.f32 %0, %1;" : "=f"(r) : "f"(x)); return r;
}
__device__ __forceinline__ float rcpf(float x) {
    float r; asm("rcp.approx.f32 %0, %1;" : "=f"(r) : "f"(x)); return r;
}
__device__ __forceinline__ u32 tf32c(float x) {
    u32 r; asm("cvt.rna.tf32.f32 %0, %1;" : "=r"(r) : "f"(x)); return r;
}
__device__ __forceinline__ float lds32(u32 a) {
    float v; asm volatile("ld.shared.f32 %0, [%1];" : "=f"(v) : "r"(a)); return v;
}
__device__ __forceinline__ void sts64(u32 a, float x, float y) {
    asm volatile("st.shared.v2.f32 [%0], {%1, %2};" :: "r"(a), "f"(x), "f"(y) : "memory");
}
__device__ __forceinline__ void cp16(u32 d, const float* s) {
    asm volatile("cp.async.ca.shared.global [%0], [%1], 16;" :: "r"(d), "l"(s) : "memory");
}
__device__ __forceinline__ void cp_commit() {
    asm volatile("cp.async.commit_group;" ::: "memory");
}
// D = A(tf32 m16k8) @ B(tf32 k8n8) + C
__device__ __forceinline__ void mma8(float& d0, float& d1, float& d2, float& d3,
                                     u32 a0, u32 a1, u32 a2, u32 a3,
                                     u32 b0, u32 b1,
                                     float c0, float c1, float c2, float c3)
{
    asm volatile("mma.sync.aligned.m16n8k8.row.col.f32.tf32.tf32.f32 "
        "{%0,%1,%2,%3}, {%4,%5,%6,%7}, {%8,%9}, {%10,%11,%12,%13};"
        : "=f"(d0), "=f"(d1), "=f"(d2), "=f"(d3)
        : "r"(a0), "r"(a1), "r"(a2), "r"(a3), "r"(b0), "r"(b1),
          "f"(c0), "f"(c1), "f"(c2), "f"(c3));
}

__global__ __launch_bounds__(128)
void lstm_mma_kernel(const float* __restrict__ x,
                     const float* __restrict__ Wi,
                     const float* __restrict__ Wh,
                     const float* __restrict__ bias,
                     const float* __restrict__ Wd,
                     const float* __restrict__ bd,
                     float* __restrict__ out)
{
    __shared__ __align__(16) float xsm[4][4][16 * RS];   // 4-slot x ring / warp
    __shared__ __align__(16) float hsm[4][2][16 * RS];   // double-buffered h / warp

    const int wib  = threadIdx.x >> 5;
    const int lane = threadIdx.x & 31;
    const int gid  = lane >> 2;      // groupID (row r)
    const int tig  = lane & 3;       // thread in group
    const int e0   = blockIdx.x * 64 + wib * 16;   // warp's 16 elements

    // ---- B fragments (tf32, pre-scaled) + bias C-init values ----
    // group g covers gate cols 8g..8g+7; scale 0.5 for i/f/o (sig), 1 for g (tanh)
    u32 Bx[8][2][2], Bh[8][2][2];
    float bc0[8], bc1[8];
#pragma unroll
    for (int g = 0; g < 8; ++g) {
        const int n = 8 * g + gid;                    // this lane's B column
        const float sc = (n < 32 || n >= 48) ? 0.5f : 1.0f;   // whole group same gate
#pragma unroll
        for (int kc = 0; kc < 2; ++kc) {
            Bx[g][kc][0] = tf32c(Wi[(kc * 8 + tig)     * NG + n] * sc);
            Bx[g][kc][1] = tf32c(Wi[(kc * 8 + tig + 4) * NG + n] * sc);
            Bh[g][kc][0] = tf32c(Wh[(kc * 8 + tig)     * NG + n] * sc);
            Bh[g][kc][1] = tf32c(Wh[(kc * 8 + tig + 4) * NG + n] * sc);
        }
        const int n0 = 8 * g + 2 * tig;               // this lane's C columns
        bc0[g] = bias[n0]     * sc;
        bc1[g] = bias[n0 + 1] * sc;
    }

    const u32 xbase = smem_u32(&xsm[wib][0][0]);
    const u32 hbase = smem_u32(&hsm[wib][0][0]);
    const u32 laneA = (u32)((gid * RS + tig) * 4);             // A-frag a0 offset
    const u32 hwb   = hbase + (u32)((gid * RS + 2 * tig) * 4); // h C-write base

    // x fetch roles: lane L -> elem L/2, k-half (L&1)*8 (8 floats = 2 cp16)
    const float* xg0 = x + (size_t)(e0 + (lane >> 1)) * (NT * ND) + (lane & 1) * 8;
    const u32 xfd = xbase + (u32)(((lane >> 1) * RS + (lane & 1) * 8) * 4);

    // h(0) = 0 in buffer 0 (each lane covers its 8 write slots)
    sts64(hwb + 0,   0.f, 0.f);
    sts64(hwb + 32,  0.f, 0.f);
    sts64(hwb + 640, 0.f, 0.f);
    sts64(hwb + 672, 0.f, 0.f);

    // prologue: x(0) -> slot 0, x(1) -> slot 1
    cp16(xfd, xg0);                    cp16(xfd + 16, xg0 + 4);           cp_commit();
    cp16(xfd + SLOT_B, xg0 + ND);      cp16(xfd + SLOT_B + 16, xg0 + ND + 4); cp_commit();

    float cst[8];
#pragma unroll
    for (int i = 0; i < 8; ++i) cst[i] = 0.f;

    // one step; s = t & 7 (compile-time). mode: 0 fetch+wait1, 1 wait0, 2 none.
    auto step = [&](int s, int mode, const float* xgp) {
        if (mode == 0) {
            const int ds = (s + 2) & 3;
            cp16(xfd + (u32)(ds * SLOT_B),      xgp + s * ND);
            cp16(xfd + (u32)(ds * SLOT_B) + 16, xgp + s * ND + 4);
            cp_commit();
            asm volatile("cp.async.wait_group 1;" ::: "memory");
        } else if (mode == 1) {
            asm volatile("cp.async.wait_group 0;" ::: "memory");
        }
        __syncwarp();

        // A fragments (f32 loads -> tf32). offsets: row+8 = 640B, col+4 = 16B, k+8 = 32B
        const u32 xb = xbase + (u32)((s & 3) * SLOT_B) + laneA;
        const u32 hb = hbase + (u32)((s & 1) * SLOT_B) + laneA;
        u32 ax[8], ah[8];
        ax[0] = tf32c(lds32(xb + 0));   ax[1] = tf32c(lds32(xb + 640));
        ax[2] = tf32c(lds32(xb + 16));  ax[3] = tf32c(lds32(xb + 656));
        ax[4] = tf32c(lds32(xb + 32));  ax[5] = tf32c(lds32(xb + 672));
        ax[6] = tf32c(lds32(xb + 48));  ax[7] = tf32c(lds32(xb + 688));
        ah[0] = tf32c(lds32(hb + 0));   ah[1] = tf32c(lds32(hb + 640));
        ah[2] = tf32c(lds32(hb + 16));  ah[3] = tf32c(lds32(hb + 656));
        ah[4] = tf32c(lds32(hb + 32));  ah[5] = tf32c(lds32(hb + 672));
        ah[6] = tf32c(lds32(hb + 48));  ah[7] = tf32c(lds32(hb + 688));

        // z = x@Wi + h@Wh + b, 4 chained mma per gate-group
        float z[8][4];
#pragma unroll
        for (int g = 0; g < 8; ++g) {
            float d0, d1, d2, d3;
            mma8(d0, d1, d2, d3, ax[0], ax[1], ax[2], ax[3],
                 Bx[g][0][0], Bx[g][0][1], bc0[g], bc1[g], bc0[g], bc1[g]);
            mma8(d0, d1, d2, d3, ax[4], ax[5], ax[6], ax[7],
                 Bx[g][1][0], Bx[g][1][1], d0, d1, d2, d3);
            mma8(d0, d1, d2, d3, ah[0], ah[1], ah[2], ah[3],
                 Bh[g][0][0], Bh[g][0][1], d0, d1, d2, d3);
            mma8(d0, d1, d2, d3, ah[4], ah[5], ah[6], ah[7],
                 Bh[g][1][0], Bh[g][1][1], d0, d1, d2, d3);
            z[g][0] = d0; z[g][1] = d1; z[g][2] = d2; z[g][3] = d3;
        }

        // activations: 8 (e,j) pairs per lane; gates of (e,j) are frags {gj, gj+2, gj+4, gj+6}
        const u32 hw = hwb + (u32)(((s & 1) ^ 1) * SLOT_B);
        float hv[8];
#pragma unroll
        for (int gj = 0; gj < 2; ++gj)
#pragma unroll
        for (int sl = 0; sl < 4; ++sl) {
            float vI = fmaf(0.5f, tanhap(z[gj    ][sl]), 0.5f);
            float vF = fmaf(0.5f, tanhap(z[gj + 2][sl]), 0.5f);
            float vG = tanhap(z[gj + 4][sl]);
            float vO = fmaf(0.5f, tanhap(z[gj + 6][sl]), 0.5f);
            const int ix = gj * 4 + sl;
            cst[ix] = fmaf(vF, cst[ix], vI * vG);
            hv[ix]  = vO * tanhap(cst[ix]);
        }
        // h(t+1): pairs (cs=0,1) -> STS.64; (gj, eo) offsets {0,32} x {0,640}
        sts64(hw + 0,   hv[0], hv[1]);
        sts64(hw + 640, hv[2], hv[3]);
        sts64(hw + 32,  hv[4], hv[5]);
        sts64(hw + 672, hv[6], hv[7]);
    };

    const float* xg = xg0 + 2 * ND;   // source base: x(tb + 2 + s)

#pragma unroll 1
    for (int tb = 0; tb < NT - 8; tb += 8) {
#pragma unroll
        for (int s = 0; s < 8; ++s)
            step(s, 0, xg);
        xg += 8 * ND;
    }
    // final block: fetches only for s<6 (t+2 <= 1023), then drain
#pragma unroll
    for (int s = 0; s < 8; ++s)
        step(s, (s < 6) ? 0 : ((s == 6) ? 1 : 2), xg);

    // ---- head: logits = c_T @ Wd + bd, softmax(2) ----
    float pa0 = 0.f, pa1 = 0.f, pb0 = 0.f, pb1 = 0.f;   // e=gid / e=gid+8
#pragma unroll
    for (int gj = 0; gj < 2; ++gj)
#pragma unroll
    for (int cs = 0; cs < 2; ++cs) {
        const int jj = 8 * gj + 2 * tig + cs;
        const float w0 = Wd[jj * 2], w1 = Wd[jj * 2 + 1];
        pa0 += cst[gj * 4 + cs] * w0;      pa1 += cst[gj * 4 + cs] * w1;
        pb0 += cst[gj * 4 + 2 + cs] * w0;  pb1 += cst[gj * 4 + 2 + cs] * w1;
    }
#pragma unroll
    for (int off = 1; off <= 2; off <<= 1) {
        pa0 += __shfl_xor_sync(0xffffffffu, pa0, off);
        pa1 += __shfl_xor_sync(0xffffffffu, pa1, off);
        pb0 += __shfl_xor_sync(0xffffffffu, pb0, off);
        pb1 += __shfl_xor_sync(0xffffffffu, pb1, off);
    }
    if (tig == 0) {
        const float L2E = 1.44269504088896340736f;
        const float b0 = bd[0], b1 = bd[1];
        {
            const int e = e0 + gid;
            float l0 = pa0 + b0, l1 = pa1 + b1;
            float mx = fmaxf(l0, l1);
            float q0 = ex2f((l0 - mx) * L2E);
            float q1 = ex2f((l1 - mx) * L2E);
            float inv = rcpf(q0 + q1);
            out[2 * e]     = q0 * inv;
            out[2 * e + 1] = q1 * inv;
        }
        {
            const int e = e0 + gid + 8;
            float l0 = pb0 + b0, l1 = pb1 + b1;
            float mx = fmaxf(l0, l1);
            float q0 = ex2f((l0 - mx) * L2E);
            float q1 = ex2f((l1 - mx) * L2E);
            float inv = rcpf(q0 + q1);
            out[2 * e]     = q0 * inv;
            out[2 * e + 1] = q1 * inv;
        }
    }
}

extern "C" void kernel_launch(void* const* d_in, const int* in_sizes, int n_in,
                              void* d_out, int out_size)
{
    const float* x  = (const float*)d_in[0];
    const float* Wi = (const float*)d_in[1];
    const float* Wh = (const float*)d_in[2];
    const float* b  = (const float*)d_in[3];
    const float* Wd = (const float*)d_in[4];
    const float* bd = (const float*)d_in[5];
    float* out = (float*)d_out;

    lstm_mma_kernel<<<NB / 64, 128>>>(x, Wi, Wh, b, Wd, bd, out);
}

// round 15
// speedup vs baseline: 2.1530x; 1.1200x over previous
#include <cuda_runtime.h>
#include <cstdint>

// CarryLSTMModel: B=8192, T=1024, D=16, H=16 (4H=64 gates, order i,f,g,o)
// Tensor-core (tf32 mma.sync.m16n8k8), M=8 variant for 2x occupancy:
//   1 warp = 8 batch elements; A-fragment rows 8-15 duplicate rows 0-7
//   (a1=a0, a3=a2 -> no extra LDS, outputs c2/c3 ignored). Tensor work per
//   element doubles, but tensor pipe was 21% busy -> affordable. Warp count
//   doubles to 1024 (256 CTAs, ~2 warps/SMSP): independent recurrence chains
//   overlap each other's serial tails.
//   Per step: z[8x64] = x[8x16]@Wi + h[8x16]@Wh + b via 32 HMMA; bias enters
//   as C of the first mma. Weights pre-scaled (0.5 i/f/o, 1 g):
//   sig(z)=0.5+0.5*tanh(z/2) via MUFU.TANH. Gates of (e,j) on one lane.
//   h relayout via stride-20 smem (conflict-free), double-buffered.
//   x via 4-slot cp.async ring (distance 2, wait_group 1).

#define NB 8192
#define NT 1024
#define ND 16
#define NG 64
#define RS 20                 // padded row stride (floats)
#define SLOT_B (8 * RS * 4)   // 640 bytes per 8x16 tile

typedef unsigned int u32;

__device__ __forceinline__ u32 smem_u32(const void* p) {
    return (u32)__cvta_generic_to_shared(p);
}
__device__ __forceinline__ float tanhap(float x) {
    float r; asm("tanh.approx.f32 %0, %1;" : "=f"(r) : "f"(x)); return r;
}
__device__ __forceinline__ float ex2f(float x) {
    float r; asm("ex2.approx.f32 %0, %1;" : "=f"(r) : "f"(x)); return r;
}
__device__ __forceinline__ float rcpf(float x) {
    float r; asm("rcp.approx.f32 %0, %1;" : "=f"(r) : "f"(x)); return r;
}
__device__ __forceinline__ u32 tf32c(float x) {
    u32 r; asm("cvt.rna.tf32.f32 %0, %1;" : "=r"(r) : "f"(x)); return r;
}
__device__ __forceinline__ float lds32(u32 a) {
    float v; asm volatile("ld.shared.f32 %0, [%1];" : "=f"(v) : "r"(a)); return v;
}
__device__ __forceinline__ void sts64(u32 a, float x, float y) {
    asm volatile("st.shared.v2.f32 [%0], {%1, %2};" :: "r"(a), "f"(x), "f"(y) : "memory");
}
__device__ __forceinline__ void cp16(u32 d, const float* s) {
    asm volatile("cp.async.ca.shared.global [%0], [%1], 16;" :: "r"(d), "l"(s) : "memory");
}
__device__ __forceinline__ void cp_commit() {
    asm volatile("cp.async.commit_group;" ::: "memory");
}
// D = A(tf32 m16k8) @ B(tf32 k8n8) + C
__device__ __forceinline__ void mma8(float& d0, float& d1, float& d2, float& d3,
                                     u32 a0, u32 a1, u32 a2, u32 a3,
                                     u32 b0, u32 b1,
                                     float c0, float c1, float c2, float c3)
{
    asm volatile("mma.sync.aligned.m16n8k8.row.col.f32.tf32.tf32.f32 "
        "{%0,%1,%2,%3}, {%4,%5,%6,%7}, {%8,%9}, {%10,%11,%12,%13};"
        : "=f"(d0), "=f"(d1), "=f"(d2), "=f"(d3)
        : "r"(a0), "r"(a1), "r"(a2), "r"(a3), "r"(b0), "r"(b1),
          "f"(c0), "f"(c1), "f"(c2), "f"(c3));
}

__global__ __launch_bounds__(128)
void lstm_mma_kernel(const float* __restrict__ x,
                     const float* __restrict__ Wi,
                     const float* __restrict__ Wh,
                     const float* __restrict__ bias,
                     const float* __restrict__ Wd,
                     const float* __restrict__ bd,
                     float* __restrict__ out)
{
    __shared__ __align__(16) float xsm[4][4][8 * RS];   // 4-slot x ring / warp
    __shared__ __align__(16) float hsm[4][2][8 * RS];   // double-buffered h / warp

    const int wib  = threadIdx.x >> 5;
    const int lane = threadIdx.x & 31;
    const int gid  = lane >> 2;      // groupID = elem row (0..7)
    const int tig  = lane & 3;       // thread in group
    const int e0   = blockIdx.x * 32 + wib * 8;   // warp's 8 elements

    // ---- B fragments (tf32, pre-scaled) + bias C-init values ----
    u32 Bx[8][2][2], Bh[8][2][2];
    float bc0[8], bc1[8];
#pragma unroll
    for (int g = 0; g < 8; ++g) {
        const int n = 8 * g + gid;
        const float sc = (n < 32 || n >= 48) ? 0.5f : 1.0f;
#pragma unroll
        for (int kc = 0; kc < 2; ++kc) {
            Bx[g][kc][0] = tf32c(Wi[(kc * 8 + tig)     * NG + n] * sc);
            Bx[g][kc][1] = tf32c(Wi[(kc * 8 + tig + 4) * NG + n] * sc);
            Bh[g][kc][0] = tf32c(Wh[(kc * 8 + tig)     * NG + n] * sc);
            Bh[g][kc][1] = tf32c(Wh[(kc * 8 + tig + 4) * NG + n] * sc);
        }
        const int n0 = 8 * g + 2 * tig;
        bc0[g] = bias[n0]     * sc;
        bc1[g] = bias[n0 + 1] * sc;
    }

    const u32 xbase = smem_u32(&xsm[wib][0][0]);
    const u32 hbase = smem_u32(&hsm[wib][0][0]);
    const u32 laneA = (u32)((gid * RS + tig) * 4);             // A-frag a0 offset
    const u32 hwb   = hbase + (u32)((gid * RS + 2 * tig) * 4); // h write base

    // x fetch roles (lanes 0-15): elem (lane>>1), k-half (lane&1)*8
    const float* xg0 = x + (size_t)(e0 + ((lane >> 1) & 7)) * (NT * ND) + (lane & 1) * 8;
    const u32 xfd = xbase + (u32)((((lane >> 1) & 7) * RS + (lane & 1) * 8) * 4);
    const bool fl = (lane < 16);

    // h(0) = 0 in buffer 0: lane covers cols {2tig,2tig+1} and {8+2tig, 8+2tig+1}
    sts64(hwb + 0,  0.f, 0.f);
    sts64(hwb + 32, 0.f, 0.f);

    // prologue: x(0) -> slot 0, x(1) -> slot 1
    if (fl) { cp16(xfd, xg0); cp16(xfd + 16, xg0 + 4); }
    cp_commit();
    if (fl) { cp16(xfd + SLOT_B, xg0 + ND); cp16(xfd + SLOT_B + 16, xg0 + ND + 4); }
    cp_commit();

    float cst[4];
#pragma unroll
    for (int i = 0; i < 4; ++i) cst[i] = 0.f;

    // one step; s = t & 7. mode: 0 fetch+wait1, 1 wait0, 2 none.
    auto step = [&](int s, int mode, const float* xgp) {
        if (mode == 0) {
            const int ds = (s + 2) & 3;
            if (fl) {
                cp16(xfd + (u32)(ds * SLOT_B),      xgp + s * ND);
                cp16(xfd + (u32)(ds * SLOT_B) + 16, xgp + s * ND + 4);
            }
            cp_commit();
            asm volatile("cp.async.wait_group 1;" ::: "memory");
        } else if (mode == 1) {
            asm volatile("cp.async.wait_group 0;" ::: "memory");
        }
        __syncwarp();

        // A fragments (rows 8-15 duplicate rows 0-7: a1=a0, a3=a2)
        const u32 xb = xbase + (u32)((s & 3) * SLOT_B) + laneA;
        const u32 hb = hbase + (u32)((s & 1) * SLOT_B) + laneA;
        u32 ax[4], ah[4];
        ax[0] = tf32c(lds32(xb + 0));   ax[1] = tf32c(lds32(xb + 16));
        ax[2] = tf32c(lds32(xb + 32));  ax[3] = tf32c(lds32(xb + 48));
        ah[0] = tf32c(lds32(hb + 0));   ah[1] = tf32c(lds32(hb + 16));
        ah[2] = tf32c(lds32(hb + 32));  ah[3] = tf32c(lds32(hb + 48));

        // z = x@Wi + h@Wh + b; 4 chained mma per gate-group, keep d0,d1 only
        float z[8][2];
#pragma unroll
        for (int g = 0; g < 8; ++g) {
            float d0, d1, d2, d3;
            mma8(d0, d1, d2, d3, ax[0], ax[0], ax[1], ax[1],
                 Bx[g][0][0], Bx[g][0][1], bc0[g], bc1[g], bc0[g], bc1[g]);
            mma8(d0, d1, d2, d3, ax[2], ax[2], ax[3], ax[3],
                 Bx[g][1][0], Bx[g][1][1], d0, d1, d2, d3);
            mma8(d0, d1, d2, d3, ah[0], ah[0], ah[1], ah[1],
                 Bh[g][0][0], Bh[g][0][1], d0, d1, d2, d3);
            mma8(d0, d1, d2, d3, ah[2], ah[2], ah[3], ah[3],
                 Bh[g][1][0], Bh[g][1][1], d0, d1, d2, d3);
            z[g][0] = d0; z[g][1] = d1;
        }

        // activations: 4 (e,j) pairs per lane; j = 8*gj + 2*tig + cs
        const u32 hw = hwb + (u32)(((s & 1) ^ 1) * SLOT_B);
        float hv[4];
#pragma unroll
        for (int gj = 0; gj < 2; ++gj)
#pragma unroll
        for (int cs = 0; cs < 2; ++cs) {
            float vI = fmaf(0.5f, tanhap(z[gj    ][cs]), 0.5f);
            float vF = fmaf(0.5f, tanhap(z[gj + 2][cs]), 0.5f);
            float vG = tanhap(z[gj + 4][cs]);
            float vO = fmaf(0.5f, tanhap(z[gj + 6][cs]), 0.5f);
            const int ix = gj * 2 + cs;
            cst[ix] = fmaf(vF, cst[ix], vI * vG);
            hv[ix]  = vO * tanhap(cst[ix]);
        }
        sts64(hw + 0,  hv[0], hv[1]);    // cols 2tig, 2tig+1
        sts64(hw + 32, hv[2], hv[3]);    // cols 8+2tig, 8+2tig+1
    };

    const float* xg = xg0 + 2 * ND;   // source base: x(tb + 2 + s)

#pragma unroll 1
    for (int tb = 0; tb < NT - 8; tb += 8) {
#pragma unroll
        for (int s = 0; s < 8; ++s)
            step(s, 0, xg);
        xg += 8 * ND;
    }
    // final block: fetches while t+2 <= 1023, then drain
#pragma unroll
    for (int s = 0; s < 8; ++s)
        step(s, (s < 6) ? 0 : ((s == 6) ? 1 : 2), xg);

    // ---- head: logits = c_T @ Wd + bd, softmax(2); elem = e0 + gid ----
    float p0 = 0.f, p1 = 0.f;
#pragma unroll
    for (int gj = 0; gj < 2; ++gj)
#pragma unroll
    for (int cs = 0; cs < 2; ++cs) {
        const int jj = 8 * gj + 2 * tig + cs;
        p0 += cst[gj * 2 + cs] * Wd[jj * 2];
        p1 += cst[gj * 2 + cs] * Wd[jj * 2 + 1];
    }
#pragma unroll
    for (int off = 1; off <= 2; off <<= 1) {
        p0 += __shfl_xor_sync(0xffffffffu, p0, off);
        p1 += __shfl_xor_sync(0xffffffffu, p1, off);
    }
    if (tig == 0) {
        const float L2E = 1.44269504088896340736f;
        const int e = e0 + gid;
        float l0 = p0 + bd[0];
        float l1 = p1 + bd[1];
        float mx = fmaxf(l0, l1);
        float q0 = ex2f((l0 - mx) * L2E);
        float q1 = ex2f((l1 - mx) * L2E);
        float inv = rcpf(q0 + q1);
        out[2 * e]     = q0 * inv;
        out[2 * e + 1] = q1 * inv;
    }
}

extern "C" void kernel_launch(void* const* d_in, const int* in_sizes, int n_in,
                              void* d_out, int out_size)
{
    const float* x  = (const float*)d_in[0];
    const float* Wi = (const float*)d_in[1];
    const float* Wh = (const float*)d_in[2];
    const float* b  = (const float*)d_in[3];
    const float* Wd = (const float*)d_in[4];
    const float* bd = (const float*)d_in[5];
    float* out = (float*)d_out;

    lstm_mma_kernel<<<NB / 32, 128>>>(x, Wi, Wh, b, Wd, bd, out);
}